// round 1
// baseline (speedup 1.0000x reference)
#include <cuda_runtime.h>
#include <cuda_bf16.h>
#include <cstddef>

#define G   20000
#define BSZ 256
#define NNZ 640000
#define H1  1024
#define H2  128
#define NCLS 33
#define KSPLIT 5
#define KCHUNK 4000   // 20000 / 5, divisible by 16

// ---------------- scratch (static __device__, allowed) ----------------
__device__ float d_hs[(size_t)G * BSZ];
__device__ float d_ht[(size_t)G * BSZ];
__device__ float d_ta[(size_t)G * BSZ];   // spmm tmp s (iter1) -> later hadamard
__device__ float d_tb[(size_t)G * BSZ];   // spmm tmp t (iter1)
__device__ float d_tc[(size_t)G * BSZ];   // spmm out s (iter2)
__device__ float d_td[(size_t)G * BSZ];   // spmm out t (iter2)

__device__ int   d_cnt[2][G];
__device__ int   d_rp [2][G + 1];
__device__ int   d_ofs[2][G];
__device__ int   d_ci [2][NNZ];
__device__ float d_cv [2][NNZ];

__device__ float d_part[(size_t)KSPLIT * BSZ * H1];
__device__ float d_h1[(size_t)BSZ * H1];
__device__ float d_h2[(size_t)BSZ * H2];

// ---------------- embed: affine+relu + transpose [B,G] -> [G,B] ----------------
__global__ void k_embed(const float* __restrict__ xs_in, const float* __restrict__ xt_in,
                        const float* __restrict__ em, const float* __restrict__ bm,
                        const float* __restrict__ ee, const float* __restrict__ be) {
    __shared__ float s0[32][33];
    __shared__ float s1[32][33];
    const float EM = em[0], BM = bm[0], EE = ee[0], BE = be[0];
    int g0 = blockIdx.x * 32;
    int b0 = blockIdx.y * 32;
    int tx = threadIdx.x, ty = threadIdx.y;
#pragma unroll
    for (int r = 0; r < 4; r++) {
        int b = b0 + ty + r * 8;
        int g = g0 + tx;
        size_t idx = (size_t)b * G + g;
        s0[ty + r * 8][tx] = xs_in[idx];
        s1[ty + r * 8][tx] = xt_in[idx];
    }
    __syncthreads();
#pragma unroll
    for (int r = 0; r < 4; r++) {
        int g = g0 + ty + r * 8;
        int b = b0 + tx;
        size_t idx = (size_t)g * BSZ + b;
        d_hs[idx] = fmaxf(fmaf(EM, s0[tx][ty + r * 8], BM), 0.f);
        d_ht[idx] = fmaxf(fmaf(EE, s1[tx][ty + r * 8], BE), 0.f);
    }
}

// ---------------- CSR build ----------------
__global__ void k_zero_cnt() {
    int i = blockIdx.x * blockDim.x + threadIdx.x;
    if (i < 2 * G) ((int*)d_cnt)[i] = 0;
}

__global__ void k_hist(const int* __restrict__ r0, const int* __restrict__ r1) {
    int i = blockIdx.x * blockDim.x + threadIdx.x;
    if (i < NNZ) {
        atomicAdd(&d_cnt[0][r0[i]], 1);
    } else if (i < 2 * NNZ) {
        atomicAdd(&d_cnt[1][r1[i - NNZ]], 1);
    }
}

__global__ void k_scan() {
    const int CH = 20;  // 1024 * 20 >= G
    int m = blockIdx.x;
    int t = threadIdx.x;
    __shared__ int sums[1024];
    int s = 0;
#pragma unroll
    for (int i = 0; i < CH; i++) {
        int idx = t * CH + i;
        if (idx < G) s += d_cnt[m][idx];
    }
    sums[t] = s;
    __syncthreads();
    for (int off = 1; off < 1024; off <<= 1) {
        int v = (t >= off) ? sums[t - off] : 0;
        __syncthreads();
        sums[t] += v;
        __syncthreads();
    }
    int run = (t == 0) ? 0 : sums[t - 1];
#pragma unroll
    for (int i = 0; i < CH; i++) {
        int idx = t * CH + i;
        if (idx < G) {
            int c = d_cnt[m][idx];
            d_rp[m][idx]  = run;
            d_ofs[m][idx] = run;
            run += c;
        }
    }
    if (t == 1023) d_rp[m][G] = NNZ;
}

__global__ void k_scatter(const int* __restrict__ r0, const int* __restrict__ c0, const float* __restrict__ v0,
                          const int* __restrict__ r1, const int* __restrict__ c1, const float* __restrict__ v1) {
    int i = blockIdx.x * blockDim.x + threadIdx.x;
    if (i < NNZ) {
        int r = r0[i];
        int p = atomicAdd(&d_ofs[0][r], 1);
        d_ci[0][p] = c0[i];
        d_cv[0][p] = 0.9f * v0[i];     // fold (1-alpha) into the matrix
    } else if (i < 2 * NNZ) {
        int j = i - NNZ;
        int r = r1[j];
        int p = atomicAdd(&d_ofs[1][r], 1);
        d_ci[1][p] = c1[j];
        d_cv[1][p] = 0.9f * v1[j];
    }
}

// ---------------- SpMM: y[r,:] = sum_j val * x[col,:], both matrices in one grid ----------------
__global__ void k_spmm_dual(int phase) {
    int bid = blockIdx.x;
    int m = (bid >= G) ? 1 : 0;
    int r = bid - m * G;
    const float* __restrict__ x;
    float* __restrict__ y;
    if (phase == 0) { x = m ? d_ht : d_hs; y = m ? d_tb : d_ta; }
    else            { x = m ? d_tb : d_ta; y = m ? d_td : d_tc; }

    int s = d_rp[m][r], e = d_rp[m][r + 1];
    int tid = threadIdx.x;
    float acc = 0.f;
    int j = s;
    for (; j + 3 < e; j += 4) {
        int   c0 = d_ci[m][j],     c1 = d_ci[m][j + 1];
        int   c2 = d_ci[m][j + 2], c3 = d_ci[m][j + 3];
        float v0 = d_cv[m][j],     v1 = d_cv[m][j + 1];
        float v2 = d_cv[m][j + 2], v3 = d_cv[m][j + 3];
        float x0 = x[(size_t)c0 * BSZ + tid];
        float x1 = x[(size_t)c1 * BSZ + tid];
        float x2 = x[(size_t)c2 * BSZ + tid];
        float x3 = x[(size_t)c3 * BSZ + tid];
        acc = fmaf(v0, x0, acc);
        acc = fmaf(v1, x1, acc);
        acc = fmaf(v2, x2, acc);
        acc = fmaf(v3, x3, acc);
    }
    for (; j < e; j++)
        acc = fmaf(d_cv[m][j], x[(size_t)d_ci[m][j] * BSZ + tid], acc);
    y[(size_t)r * BSZ + tid] = acc;
}

// ---------------- combine: hadamard in [G,B] layout (column-major A for GEMM) ----------------
__global__ void k_combine() {
    int i = blockIdx.x * blockDim.x + threadIdx.x;   // over G*B/4
    const float4* tc = (const float4*)d_tc;
    const float4* td = (const float4*)d_td;
    const float4* hs = (const float4*)d_hs;
    const float4* ht = (const float4*)d_ht;
    float4 a = tc[i], h = hs[i];
    float4 b = td[i], g = ht[i];
    float4 o;
    o.x = (a.x + 0.1f * h.x) * (b.x + 0.1f * g.x);
    o.y = (a.y + 0.1f * h.y) * (b.y + 0.1f * g.y);
    o.z = (a.z + 0.1f * h.z) * (b.z + 0.1f * g.z);
    o.w = (a.w + 0.1f * h.w) * (b.w + 0.1f * g.w);
    ((float4*)d_ta)[i] = o;   // reuse ta as hadamard buffer
}

// ---------------- GEMM1: h1_part = had(A, K-major col-major) @ W1^T, split-K ----------------
__global__ void k_gemm1(const float* __restrict__ W1) {
    __shared__ float As[16][65];
    __shared__ float Bs[16][65];
    int m0 = blockIdx.x * 64;
    int n0 = blockIdx.y * 64;
    int z  = blockIdx.z;
    int k0 = z * KCHUNK;
    int tid = threadIdx.x;
    int tx = tid & 15, ty = tid >> 4;
    int am = tid & 63, ak = tid >> 6;   // A load coords
    int bk = tid & 15, bn = tid >> 4;   // B load coords
    float acc[4][4] = {};
    const float* __restrict__ A = d_ta;

    for (int kt = 0; kt < KCHUNK / 16; kt++) {
        int kb = k0 + kt * 16;
#pragma unroll
        for (int p = 0; p < 4; p++)
            As[ak + p * 4][am] = A[(size_t)(kb + ak + p * 4) * BSZ + m0 + am];
#pragma unroll
        for (int p = 0; p < 4; p++)
            Bs[bk][bn + p * 16] = W1[(size_t)(n0 + bn + p * 16) * G + kb + bk];
        __syncthreads();
#pragma unroll
        for (int kk = 0; kk < 16; kk++) {
            float a[4], b[4];
#pragma unroll
            for (int i = 0; i < 4; i++) a[i] = As[kk][tx * 4 + i];
#pragma unroll
            for (int j = 0; j < 4; j++) b[j] = Bs[kk][ty * 4 + j];
#pragma unroll
            for (int i = 0; i < 4; i++)
#pragma unroll
                for (int j = 0; j < 4; j++)
                    acc[i][j] = fmaf(a[i], b[j], acc[i][j]);
        }
        __syncthreads();
    }
    float* out = d_part + (size_t)z * BSZ * H1;
#pragma unroll
    for (int i = 0; i < 4; i++)
#pragma unroll
        for (int j = 0; j < 4; j++)
            out[(size_t)(m0 + tx * 4 + i) * H1 + n0 + ty * 4 + j] = acc[i][j];
}

__global__ void k_reduce1(const float* __restrict__ b1) {
    int i = blockIdx.x * blockDim.x + threadIdx.x;   // over 256*1024
    int n = i & (H1 - 1);
    float s = b1[n];
#pragma unroll
    for (int z = 0; z < KSPLIT; z++)
        s += d_part[(size_t)z * BSZ * H1 + i];
    d_h1[i] = fmaxf(s, 0.f);
}

// ---------------- GEMM2: h2 = relu(h1 @ W2^T + b2) ----------------
__global__ void k_gemm2(const float* __restrict__ W2, const float* __restrict__ b2) {
    __shared__ float sh[H1];
    int b = blockIdx.x;
    int n = threadIdx.x;   // 128 threads
    for (int k = n; k < H1; k += H2)
        sh[k] = d_h1[(size_t)b * H1 + k];
    __syncthreads();
    float acc = b2[n];
    const float4* w = (const float4*)(W2 + (size_t)n * H1);
#pragma unroll 4
    for (int kk = 0; kk < H1 / 4; kk++) {
        float4 wv = w[kk];
        acc = fmaf(wv.x, sh[kk * 4 + 0], acc);
        acc = fmaf(wv.y, sh[kk * 4 + 1], acc);
        acc = fmaf(wv.z, sh[kk * 4 + 2], acc);
        acc = fmaf(wv.w, sh[kk * 4 + 3], acc);
    }
    d_h2[(size_t)b * H2 + n] = fmaxf(acc, 0.f);
}

// ---------------- GEMM3: out = h2 @ W3^T + b3 ----------------
__global__ void k_gemm3(const float* __restrict__ W3, const float* __restrict__ b3,
                        float* __restrict__ out) {
    __shared__ float sh[H2];
    int b = blockIdx.x;
    int tid = threadIdx.x;   // 128 threads
    sh[tid] = d_h2[(size_t)b * H2 + tid];
    __syncthreads();
    if (tid < NCLS) {
        float acc = b3[tid];
        const float* w = W3 + (size_t)tid * H2;
#pragma unroll 4
        for (int k = 0; k < H2; k++)
            acc = fmaf(w[k], sh[k], acc);
        out[(size_t)b * NCLS + tid] = acc;
    }
}

// ---------------- launch ----------------
extern "C" void kernel_launch(void* const* d_in, const int* in_sizes, int n_in,
                              void* d_out, int out_size) {
    const float* x_sample  = (const float*)d_in[0];
    const float* x_TF      = (const float*)d_in[1];
    const int*   adj_rows  = (const int*)  d_in[2];
    const int*   adj_cols  = (const int*)  d_in[3];
    const float* adj_vals  = (const float*)d_in[4];
    const int*   adjT_rows = (const int*)  d_in[5];
    const int*   adjT_cols = (const int*)  d_in[6];
    const float* adjT_vals = (const float*)d_in[7];
    const float* emb_mut   = (const float*)d_in[8];
    const float* bias_mut  = (const float*)d_in[9];
    const float* emb_exp   = (const float*)d_in[10];
    const float* bias_exp  = (const float*)d_in[11];
    const float* W1        = (const float*)d_in[12];
    const float* b1        = (const float*)d_in[13];
    const float* W2        = (const float*)d_in[14];
    const float* b2        = (const float*)d_in[15];
    const float* W3        = (const float*)d_in[16];
    const float* b3        = (const float*)d_in[17];
    float* out = (float*)d_out;

    // embed + transpose
    k_embed<<<dim3(G / 32, BSZ / 32), dim3(32, 8)>>>(x_sample, x_TF,
                                                     emb_mut, bias_mut, emb_exp, bias_exp);
    // CSR build
    k_zero_cnt<<<(2 * G + 255) / 256, 256>>>();
    k_hist<<<(2 * NNZ + 255) / 256, 256>>>(adj_rows, adjT_rows);
    k_scan<<<2, 1024>>>();
    k_scatter<<<(2 * NNZ + 255) / 256, 256>>>(adj_rows, adj_cols, adj_vals,
                                              adjT_rows, adjT_cols, adjT_vals);
    // PPR: two SpMM rounds for both matrices
    k_spmm_dual<<<2 * G, BSZ>>>(0);
    k_spmm_dual<<<2 * G, BSZ>>>(1);
    // hadamard with alpha restart
    k_combine<<<(G * BSZ / 4) / 256, 256>>>();
    // MLP
    k_gemm1<<<dim3(BSZ / 64, H1 / 64, KSPLIT), 256>>>(W1);
    k_reduce1<<<(BSZ * H1) / 256, 256>>>(b1);
    k_gemm2<<<BSZ, H2>>>(W2, b2);
    k_gemm3<<<BSZ, H2>>>(W3, b3, out);
}

// round 2
// speedup vs baseline: 2.1483x; 2.1483x over previous
#include <cuda_runtime.h>
#include <cuda_bf16.h>
#include <cstddef>
#include <cstdint>

#define G    20000
#define BSZ  256
#define NNZ  640000
#define H1   1024
#define H2   128
#define NCLS 33

// GEMM1 tiling
#define BM 128
#define BN 128
#define BK 32
#define ZSPLIT 25
#define KC 800          // 20000 / 25, divisible by 32
#define LDA 132
#define LDB 132

// ---------------- scratch ----------------
__device__ float d_hs[(size_t)G * BSZ];
__device__ float d_ht[(size_t)G * BSZ];
__device__ float d_ta[(size_t)G * BSZ];   // spmm tmp s (iter1) -> later hadamard
__device__ float d_tb[(size_t)G * BSZ];
__device__ float d_tc[(size_t)G * BSZ];
__device__ float d_td[(size_t)G * BSZ];

__device__ int   d_cnt[2][G];
__device__ int   d_rp [2][G + 1];
__device__ int   d_ofs[2][G];
__device__ int   d_ci [2][NNZ];
__device__ float d_cv [2][NNZ];

__device__ float d_part[(size_t)ZSPLIT * BSZ * H1];
__device__ float d_h1[(size_t)BSZ * H1];
__device__ float d_h2[(size_t)BSZ * H2];

// ---------------- embed: affine+relu + transpose [B,G] -> [G,B] ----------------
__global__ void k_embed(const float* __restrict__ xs_in, const float* __restrict__ xt_in,
                        const float* __restrict__ em, const float* __restrict__ bm,
                        const float* __restrict__ ee, const float* __restrict__ be) {
    __shared__ float s0[32][33];
    __shared__ float s1[32][33];
    const float EM = em[0], BM_ = bm[0], EE = ee[0], BE = be[0];
    int g0 = blockIdx.x * 32;
    int b0 = blockIdx.y * 32;
    int tx = threadIdx.x, ty = threadIdx.y;
#pragma unroll
    for (int r = 0; r < 4; r++) {
        int b = b0 + ty + r * 8;
        int g = g0 + tx;
        size_t idx = (size_t)b * G + g;
        s0[ty + r * 8][tx] = xs_in[idx];
        s1[ty + r * 8][tx] = xt_in[idx];
    }
    __syncthreads();
#pragma unroll
    for (int r = 0; r < 4; r++) {
        int g = g0 + ty + r * 8;
        int b = b0 + tx;
        size_t idx = (size_t)g * BSZ + b;
        d_hs[idx] = fmaxf(fmaf(EM, s0[tx][ty + r * 8], BM_), 0.f);
        d_ht[idx] = fmaxf(fmaf(EE, s1[tx][ty + r * 8], BE), 0.f);
    }
}

// ---------------- CSR build ----------------
__global__ void k_zero_cnt() {
    int i = blockIdx.x * blockDim.x + threadIdx.x;
    if (i < 2 * G) ((int*)d_cnt)[i] = 0;
}

__global__ void k_hist(const int* __restrict__ r0, const int* __restrict__ r1) {
    int i = blockIdx.x * blockDim.x + threadIdx.x;
    if (i < NNZ) {
        atomicAdd(&d_cnt[0][r0[i]], 1);
    } else if (i < 2 * NNZ) {
        atomicAdd(&d_cnt[1][r1[i - NNZ]], 1);
    }
}

// shuffle-based block scan, 1024 threads, 20 elements/thread
__global__ void k_scan() {
    const int CH = 20;
    int m = blockIdx.x;
    int t = threadIdx.x;
    int lane = t & 31, w = t >> 5;
    int base = t * CH;
    int c[CH];
    int s = 0;
#pragma unroll
    for (int i = 0; i < CH; i++) {
        int idx = base + i;
        c[i] = (idx < G) ? d_cnt[m][idx] : 0;
        s += c[i];
    }
    // warp inclusive scan
    int v = s;
#pragma unroll
    for (int off = 1; off < 32; off <<= 1) {
        int u = __shfl_up_sync(0xffffffffu, v, off);
        if (lane >= off) v += u;
    }
    __shared__ int wsum[32];
    if (lane == 31) wsum[w] = v;
    __syncthreads();
    if (w == 0) {
        int x = wsum[lane];
#pragma unroll
        for (int off = 1; off < 32; off <<= 1) {
            int u = __shfl_up_sync(0xffffffffu, x, off);
            if (lane >= off) x += u;
        }
        wsum[lane] = x;
    }
    __syncthreads();
    int run = v - s + ((w > 0) ? wsum[w - 1] : 0);   // exclusive prefix for this thread
#pragma unroll
    for (int i = 0; i < CH; i++) {
        int idx = base + i;
        if (idx < G) {
            d_rp[m][idx]  = run;
            d_ofs[m][idx] = run;
            run += c[i];
        }
    }
    if (t == 1023) d_rp[m][G] = NNZ;
}

__global__ void k_scatter(const int* __restrict__ r0, const int* __restrict__ c0, const float* __restrict__ v0,
                          const int* __restrict__ r1, const int* __restrict__ c1, const float* __restrict__ v1) {
    int i = blockIdx.x * blockDim.x + threadIdx.x;
    if (i < NNZ) {
        int r = r0[i];
        int p = atomicAdd(&d_ofs[0][r], 1);
        d_ci[0][p] = c0[i];
        d_cv[0][p] = 0.9f * v0[i];
    } else if (i < 2 * NNZ) {
        int j = i - NNZ;
        int r = r1[j];
        int p = atomicAdd(&d_ofs[1][r], 1);
        d_ci[1][p] = c1[j];
        d_cv[1][p] = 0.9f * v1[j];
    }
}

// ---------------- SpMM: 4 rows/CTA, float4 per thread ----------------
__global__ void k_spmm_dual(int phase) {
    int tid = threadIdx.x;
    int gr = blockIdx.x * 4 + (tid >> 6);   // global row 0..2G-1
    int cq = tid & 63;                       // float4 column group
    int m = (gr >= G) ? 1 : 0;
    int r = gr - m * G;
    const float* __restrict__ x;
    float* __restrict__ y;
    if (phase == 0) { x = m ? d_ht : d_hs; y = m ? d_tb : d_ta; }
    else            { x = m ? d_tb : d_ta; y = m ? d_td : d_tc; }
    const float4* __restrict__ x4 = (const float4*)x;

    int s = d_rp[m][r], e = d_rp[m][r + 1];
    float4 acc = make_float4(0.f, 0.f, 0.f, 0.f);
    int j = s;
    for (; j + 1 < e; j += 2) {
        int   c0 = d_ci[m][j],     c1 = d_ci[m][j + 1];
        float v0 = d_cv[m][j],     v1 = d_cv[m][j + 1];
        float4 x0 = x4[(size_t)c0 * 64 + cq];
        float4 x1 = x4[(size_t)c1 * 64 + cq];
        acc.x = fmaf(v0, x0.x, acc.x); acc.y = fmaf(v0, x0.y, acc.y);
        acc.z = fmaf(v0, x0.z, acc.z); acc.w = fmaf(v0, x0.w, acc.w);
        acc.x = fmaf(v1, x1.x, acc.x); acc.y = fmaf(v1, x1.y, acc.y);
        acc.z = fmaf(v1, x1.z, acc.z); acc.w = fmaf(v1, x1.w, acc.w);
    }
    if (j < e) {
        float v = d_cv[m][j]; int c = d_ci[m][j];
        float4 xv = x4[(size_t)c * 64 + cq];
        acc.x = fmaf(v, xv.x, acc.x); acc.y = fmaf(v, xv.y, acc.y);
        acc.z = fmaf(v, xv.z, acc.z); acc.w = fmaf(v, xv.w, acc.w);
    }
    ((float4*)y)[(size_t)r * 64 + cq] = acc;
}

// ---------------- combine: hadamard in [G,B] layout ----------------
__global__ void k_combine() {
    int i = blockIdx.x * blockDim.x + threadIdx.x;
    const float4* tc = (const float4*)d_tc;
    const float4* td = (const float4*)d_td;
    const float4* hs = (const float4*)d_hs;
    const float4* ht = (const float4*)d_ht;
    float4 a = tc[i], h = hs[i];
    float4 b = td[i], g = ht[i];
    float4 o;
    o.x = (a.x + 0.1f * h.x) * (b.x + 0.1f * g.x);
    o.y = (a.y + 0.1f * h.y) * (b.y + 0.1f * g.y);
    o.z = (a.z + 0.1f * h.z) * (b.z + 0.1f * g.z);
    o.w = (a.w + 0.1f * h.w) * (b.w + 0.1f * g.w);
    ((float4*)d_ta)[i] = o;
}

// ---------------- GEMM1: tf32 mma.sync, split-K ----------------
__device__ __forceinline__ float rnd_tf32(float v) {
    // round-to-nearest into tf32: add half-ulp of the 13 dropped bits;
    // the tensor core's implicit truncation completes the rounding.
    return __int_as_float(__float_as_int(v) + 0x1000);
}

__device__ __forceinline__ void mma_tf32(float& c0, float& c1, float& c2, float& c3,
                                         uint32_t a0, uint32_t a1, uint32_t a2, uint32_t a3,
                                         uint32_t b0, uint32_t b1) {
    asm volatile(
        "mma.sync.aligned.m16n8k8.row.col.f32.tf32.tf32.f32 "
        "{%0,%1,%2,%3},{%4,%5,%6,%7},{%8,%9},{%0,%1,%2,%3};"
        : "+f"(c0), "+f"(c1), "+f"(c2), "+f"(c3)
        : "r"(a0), "r"(a1), "r"(a2), "r"(a3), "r"(b0), "r"(b1));
}

__global__ void __launch_bounds__(256) k_gemm1(const float* __restrict__ W1) {
    __shared__ float As[BK][LDA];   // [k][m]
    __shared__ float Bs[BK][LDB];   // [k][n]
    const int m0 = blockIdx.x * BM;
    const int n0 = blockIdx.y * BN;
    const int kbase = blockIdx.z * KC;
    const int tid = threadIdx.x;
    const int lane = tid & 31;
    const int wid = tid >> 5;
    const int wm = (wid >> 2) * 64;
    const int wn = (wid & 3) * 32;
    const int gid = lane >> 2;
    const int tig = lane & 3;

    // A staging: thread loads float4 at m = (tid&31)*4, k = (tid>>5) + p*8
    const int am = (tid & 31) * 4;
    const int ak = tid >> 5;
    // B staging: thread loads 4 float4 for n = tid&127, k = (tid>>7)*16 + p*4
    const int bn = tid & 127;
    const int bkq = (tid >> 7) * 16;

    const float* __restrict__ A = d_ta;
    float4 ra[4], rb[4];
    float acc[4][4][4];
#pragma unroll
    for (int i = 0; i < 4; i++)
#pragma unroll
        for (int j = 0; j < 4; j++)
#pragma unroll
            for (int q = 0; q < 4; q++) acc[i][j][q] = 0.f;

    // prefetch stage 0
#pragma unroll
    for (int p = 0; p < 4; p++)
        ra[p] = *(const float4*)&A[(size_t)(kbase + ak + p * 8) * BSZ + m0 + am];
#pragma unroll
    for (int p = 0; p < 4; p++)
        rb[p] = *(const float4*)&W1[(size_t)(n0 + bn) * G + kbase + bkq + p * 4];

    const int NSTAGE = KC / BK;   // 25
    for (int s = 0; s < NSTAGE; s++) {
        __syncthreads();
        // store stage (with rna-tf32 rounding)
#pragma unroll
        for (int p = 0; p < 4; p++) {
            float4 v = ra[p];
            v.x = rnd_tf32(v.x); v.y = rnd_tf32(v.y);
            v.z = rnd_tf32(v.z); v.w = rnd_tf32(v.w);
            *(float4*)&As[ak + p * 8][am] = v;
        }
#pragma unroll
        for (int p = 0; p < 4; p++) {
            float4 v = rb[p];
            Bs[bkq + p * 4 + 0][bn] = rnd_tf32(v.x);
            Bs[bkq + p * 4 + 1][bn] = rnd_tf32(v.y);
            Bs[bkq + p * 4 + 2][bn] = rnd_tf32(v.z);
            Bs[bkq + p * 4 + 3][bn] = rnd_tf32(v.w);
        }
        __syncthreads();
        if (s + 1 < NSTAGE) {
            int kb = kbase + (s + 1) * BK;
#pragma unroll
            for (int p = 0; p < 4; p++)
                ra[p] = *(const float4*)&A[(size_t)(kb + ak + p * 8) * BSZ + m0 + am];
#pragma unroll
            for (int p = 0; p < 4; p++)
                rb[p] = *(const float4*)&W1[(size_t)(n0 + bn) * G + kb + bkq + p * 4];
        }
        // compute: 4 k-slices of 8
#pragma unroll
        for (int ks = 0; ks < 4; ks++) {
            int k0 = ks * 8;
            uint32_t af[4][4], bf[4][2];
#pragma unroll
            for (int i = 0; i < 4; i++) {
                int rm = wm + i * 16 + gid;
                af[i][0] = __float_as_uint(As[k0 + tig][rm]);
                af[i][1] = __float_as_uint(As[k0 + tig][rm + 8]);
                af[i][2] = __float_as_uint(As[k0 + tig + 4][rm]);
                af[i][3] = __float_as_uint(As[k0 + tig + 4][rm + 8]);
            }
#pragma unroll
            for (int j = 0; j < 4; j++) {
                int cn = wn + j * 8 + gid;
                bf[j][0] = __float_as_uint(Bs[k0 + tig][cn]);
                bf[j][1] = __float_as_uint(Bs[k0 + tig + 4][cn]);
            }
#pragma unroll
            for (int i = 0; i < 4; i++)
#pragma unroll
                for (int j = 0; j < 4; j++)
                    mma_tf32(acc[i][j][0], acc[i][j][1], acc[i][j][2], acc[i][j][3],
                             af[i][0], af[i][1], af[i][2], af[i][3],
                             bf[j][0], bf[j][1]);
        }
    }

    // epilogue
    float* out = d_part + (size_t)blockIdx.z * BSZ * H1;
#pragma unroll
    for (int i = 0; i < 4; i++) {
        int row = m0 + wm + i * 16 + gid;
#pragma unroll
        for (int j = 0; j < 4; j++) {
            int col = n0 + wn + j * 8 + 2 * tig;
            float2 lo = make_float2(acc[i][j][0], acc[i][j][1]);
            float2 hi = make_float2(acc[i][j][2], acc[i][j][3]);
            *(float2*)&out[(size_t)row * H1 + col] = lo;
            *(float2*)&out[(size_t)(row + 8) * H1 + col] = hi;
        }
    }
}

__global__ void k_reduce1(const float* __restrict__ b1) {
    int i = blockIdx.x * blockDim.x + threadIdx.x;
    int n = i & (H1 - 1);
    float s = b1[n];
#pragma unroll
    for (int z = 0; z < ZSPLIT; z++)
        s += d_part[(size_t)z * BSZ * H1 + i];
    d_h1[i] = fmaxf(s, 0.f);
}

// ---------------- GEMM2: 4 batches/block share W2 reads ----------------
__global__ void k_gemm2(const float* __restrict__ W2, const float* __restrict__ b2) {
    __shared__ float sh[4][H1];
    int b0 = blockIdx.x * 4;
    int n = threadIdx.x;   // 128
#pragma unroll
    for (int r = 0; r < 4; r++)
        for (int k = n; k < H1; k += H2)
            sh[r][k] = d_h1[(size_t)(b0 + r) * H1 + k];
    __syncthreads();
    float bias = b2[n];
    float a0 = bias, a1 = bias, a2 = bias, a3 = bias;
    const float4* w = (const float4*)(W2 + (size_t)n * H1);
#pragma unroll 4
    for (int kk = 0; kk < H1 / 4; kk++) {
        float4 wv = w[kk];
        a0 = fmaf(wv.x, sh[0][kk * 4 + 0], a0); a0 = fmaf(wv.y, sh[0][kk * 4 + 1], a0);
        a0 = fmaf(wv.z, sh[0][kk * 4 + 2], a0); a0 = fmaf(wv.w, sh[0][kk * 4 + 3], a0);
        a1 = fmaf(wv.x, sh[1][kk * 4 + 0], a1); a1 = fmaf(wv.y, sh[1][kk * 4 + 1], a1);
        a1 = fmaf(wv.z, sh[1][kk * 4 + 2], a1); a1 = fmaf(wv.w, sh[1][kk * 4 + 3], a1);
        a2 = fmaf(wv.x, sh[2][kk * 4 + 0], a2); a2 = fmaf(wv.y, sh[2][kk * 4 + 1], a2);
        a2 = fmaf(wv.z, sh[2][kk * 4 + 2], a2); a2 = fmaf(wv.w, sh[2][kk * 4 + 3], a2);
        a3 = fmaf(wv.x, sh[3][kk * 4 + 0], a3); a3 = fmaf(wv.y, sh[3][kk * 4 + 1], a3);
        a3 = fmaf(wv.z, sh[3][kk * 4 + 2], a3); a3 = fmaf(wv.w, sh[3][kk * 4 + 3], a3);
    }
    d_h2[(size_t)(b0 + 0) * H2 + n] = fmaxf(a0, 0.f);
    d_h2[(size_t)(b0 + 1) * H2 + n] = fmaxf(a1, 0.f);
    d_h2[(size_t)(b0 + 2) * H2 + n] = fmaxf(a2, 0.f);
    d_h2[(size_t)(b0 + 3) * H2 + n] = fmaxf(a3, 0.f);
}

// ---------------- GEMM3 ----------------
__global__ void k_gemm3(const float* __restrict__ W3, const float* __restrict__ b3,
                        float* __restrict__ out) {
    __shared__ float sh[H2];
    int b = blockIdx.x;
    int tid = threadIdx.x;
    sh[tid] = d_h2[(size_t)b * H2 + tid];
    __syncthreads();
    if (tid < NCLS) {
        float acc = b3[tid];
        const float* w = W3 + (size_t)tid * H2;
#pragma unroll 4
        for (int k = 0; k < H2; k++)
            acc = fmaf(w[k], sh[k], acc);
        out[(size_t)b * NCLS + tid] = acc;
    }
}

// ---------------- launch ----------------
extern "C" void kernel_launch(void* const* d_in, const int* in_sizes, int n_in,
                              void* d_out, int out_size) {
    const float* x_sample  = (const float*)d_in[0];
    const float* x_TF      = (const float*)d_in[1];
    const int*   adj_rows  = (const int*)  d_in[2];
    const int*   adj_cols  = (const int*)  d_in[3];
    const float* adj_vals  = (const float*)d_in[4];
    const int*   adjT_rows = (const int*)  d_in[5];
    const int*   adjT_cols = (const int*)  d_in[6];
    const float* adjT_vals = (const float*)d_in[7];
    const float* emb_mut   = (const float*)d_in[8];
    const float* bias_mut  = (const float*)d_in[9];
    const float* emb_exp   = (const float*)d_in[10];
    const float* bias_exp  = (const float*)d_in[11];
    const float* W1        = (const float*)d_in[12];
    const float* b1        = (const float*)d_in[13];
    const float* W2        = (const float*)d_in[14];
    const float* b2        = (const float*)d_in[15];
    const float* W3        = (const float*)d_in[16];
    const float* b3        = (const float*)d_in[17];
    float* out = (float*)d_out;

    k_embed<<<dim3(G / 32, BSZ / 32), dim3(32, 8)>>>(x_sample, x_TF,
                                                     emb_mut, bias_mut, emb_exp, bias_exp);
    k_zero_cnt<<<(2 * G + 255) / 256, 256>>>();
    k_hist<<<(2 * NNZ + 255) / 256, 256>>>(adj_rows, adjT_rows);
    k_scan<<<2, 1024>>>();
    k_scatter<<<(2 * NNZ + 255) / 256, 256>>>(adj_rows, adj_cols, adj_vals,
                                              adjT_rows, adjT_cols, adjT_vals);
    k_spmm_dual<<<2 * G / 4, 256>>>(0);
    k_spmm_dual<<<2 * G / 4, 256>>>(1);
    k_combine<<<(G * BSZ / 4) / 256, 256>>>();
    k_gemm1<<<dim3(BSZ / BM, H1 / BN, ZSPLIT), 256>>>(W1);
    k_reduce1<<<(BSZ * H1) / 256, 256>>>(b1);
    k_gemm2<<<BSZ / 4, H2>>>(W2, b2);
    k_gemm3<<<BSZ, H2>>>(W3, b3, out);
}

// round 3
// speedup vs baseline: 2.3606x; 1.0988x over previous
#include <cuda_runtime.h>
#include <cuda_fp16.h>
#include <cstddef>
#include <cstdint>

#define G    20000
#define BSZ  256
#define NNZ  640000
#define H1   1024
#define H2   128
#define NCLS 33

// GEMM1 tiling
#define BM 128
#define BN 128
#define BK 32
#define ZSPLIT 25
#define KC 800
#define LDA 132
#define LDB 132

#define SCANB 512
#define NBLK  40      // ceil(20000/512)

// ---------------- scratch ----------------
__device__ float d_hs[(size_t)G * BSZ];
__device__ float d_ht[(size_t)G * BSZ];
__device__ float d_ta[(size_t)G * BSZ];   // spmm s iter1 (fp32) -> later hadamard
__device__ float d_tb[(size_t)G * BSZ];
__device__ float d_tc[(size_t)G * BSZ];
__device__ float d_td[(size_t)G * BSZ];

__device__ __half d_hsh[(size_t)G * BSZ];
__device__ __half d_hth[(size_t)G * BSZ];
__device__ __half d_tah[(size_t)G * BSZ];
__device__ __half d_tbh[(size_t)G * BSZ];

__device__ int   d_cnt[2][G];
__device__ int   d_rp [2][G + 1];
__device__ int   d_ofs[2][G];
__device__ uint2 d_ce [2][NNZ];     // packed (col, valbits)
__device__ int   d_bsum[2][NBLK];
__device__ int   d_bmid[2][NBLK];

__device__ float d_part[(size_t)ZSPLIT * BSZ * H1];
__device__ float d_h1[(size_t)BSZ * H1];
__device__ float d_h2[(size_t)BSZ * H2];

// ---------------- embed: affine+relu + transpose, emit fp32 + fp16 ----------------
__global__ void k_embed(const float* __restrict__ xs_in, const float* __restrict__ xt_in,
                        const float* __restrict__ em, const float* __restrict__ bm,
                        const float* __restrict__ ee, const float* __restrict__ be) {
    __shared__ float s0[32][33];
    __shared__ float s1[32][33];
    const float EM = em[0], BM_ = bm[0], EE = ee[0], BE = be[0];
    int g0 = blockIdx.x * 32;
    int b0 = blockIdx.y * 32;
    int tx = threadIdx.x, ty = threadIdx.y;
#pragma unroll
    for (int r = 0; r < 4; r++) {
        size_t idx = (size_t)(b0 + ty + r * 8) * G + g0 + tx;
        s0[ty + r * 8][tx] = xs_in[idx];
        s1[ty + r * 8][tx] = xt_in[idx];
    }
    __syncthreads();
#pragma unroll
    for (int r = 0; r < 4; r++) {
        int g = g0 + ty + r * 8;
        int b = b0 + tx;
        size_t idx = (size_t)g * BSZ + b;
        float vs = fmaxf(fmaf(EM, s0[tx][ty + r * 8], BM_), 0.f);
        float vt = fmaxf(fmaf(EE, s1[tx][ty + r * 8], BE), 0.f);
        d_hs[idx] = vs;  d_hsh[idx] = __float2half_rn(vs);
        d_ht[idx] = vt;  d_hth[idx] = __float2half_rn(vt);
    }
}

// ---------------- CSR build ----------------
__global__ void k_zero_cnt() {
    int i = blockIdx.x * blockDim.x + threadIdx.x;
    if (i < 2 * G) ((int*)d_cnt)[i] = 0;
}

__global__ void k_hist(const int* __restrict__ r0, const int* __restrict__ r1) {
    int i = blockIdx.x * blockDim.x + threadIdx.x;
    if (i < NNZ) {
        atomicAdd(&d_cnt[0][r0[i]], 1);
    } else if (i < 2 * NNZ) {
        atomicAdd(&d_cnt[1][r1[i - NNZ]], 1);
    }
}

// pass 1: per-block exclusive scan + block totals
__global__ void k_scan_part() {
    int m = blockIdx.y;
    int tid = threadIdx.x;
    int i = blockIdx.x * SCANB + tid;
    int lane = tid & 31, w = tid >> 5;
    int c = (i < G) ? d_cnt[m][i] : 0;
    int v = c;
#pragma unroll
    for (int off = 1; off < 32; off <<= 1) {
        int u = __shfl_up_sync(0xffffffffu, v, off);
        if (lane >= off) v += u;
    }
    __shared__ int ws[16];
    if (lane == 31) ws[w] = v;
    __syncthreads();
    if (w == 0) {
        int x = (lane < 16) ? ws[lane] : 0;
#pragma unroll
        for (int off = 1; off < 16; off <<= 1) {
            int u = __shfl_up_sync(0xffffffffu, x, off);
            if (lane >= off) x += u;
        }
        if (lane < 16) ws[lane] = x;
    }
    __syncthreads();
    int excl = v - c + ((w > 0) ? ws[w - 1] : 0);
    if (i < G) d_rp[m][i] = excl;
    if (tid == SCANB - 1) d_bsum[m][blockIdx.x] = excl + c;
}

// pass 2: scan block sums (both matrices in one block)
__global__ void k_scan_mid() {
    int tid = threadIdx.x;        // 128 threads
    int m = tid >> 6;
    int t = tid & 63;
    int lane = tid & 31, warp = tid >> 5;
    int c = (t < NBLK) ? d_bsum[m][t] : 0;
    int v = c;
#pragma unroll
    for (int off = 1; off < 32; off <<= 1) {
        int u = __shfl_up_sync(0xffffffffu, v, off);
        if (lane >= off) v += u;
    }
    __shared__ int tot[4];
    if (lane == 31) tot[warp] = v;
    __syncthreads();
    int add = (warp & 1) ? tot[warp - 1] : 0;
    int excl = v - c + add;
    if (t < NBLK) d_bmid[m][t] = excl;
}

// pass 3: apply block offsets
__global__ void k_scan_add() {
    int m = blockIdx.y;
    int i = blockIdx.x * SCANB + threadIdx.x;
    int add = d_bmid[m][blockIdx.x];
    if (i < G) {
        int r = d_rp[m][i] + add;
        d_rp[m][i] = r;
        d_ofs[m][i] = r;
    }
    if (blockIdx.x == 0 && threadIdx.x == 0) d_rp[m][G] = NNZ;
}

__global__ void k_scatter(const int* __restrict__ r0, const int* __restrict__ c0, const float* __restrict__ v0,
                          const int* __restrict__ r1, const int* __restrict__ c1, const float* __restrict__ v1) {
    int i = blockIdx.x * blockDim.x + threadIdx.x;
    if (i < NNZ) {
        int r = r0[i];
        int p = atomicAdd(&d_ofs[0][r], 1);
        d_ce[0][p] = make_uint2((unsigned)c0[i], __float_as_uint(0.9f * v0[i]));
    } else if (i < 2 * NNZ) {
        int j = i - NNZ;
        int r = r1[j];
        int p = atomicAdd(&d_ofs[1][r], 1);
        d_ce[1][p] = make_uint2((unsigned)c1[j], __float_as_uint(0.9f * v1[j]));
    }
}

// ---------------- SpMM: fp16 gather, fp32 accumulate; 4 rows/CTA ----------------
template <int PHASE>
__global__ void k_spmm_dual() {
    int tid = threadIdx.x;
    int gr = blockIdx.x * 4 + (tid >> 6);
    int cq = tid & 63;                    // 4-half column group
    int m = (gr >= G) ? 1 : 0;
    int r = gr - m * G;

    const __half* __restrict__ xh;
    float* __restrict__ y;
    __half* __restrict__ yh;
    if (PHASE == 0) { xh = m ? d_hth : d_hsh; y = m ? d_tb : d_ta; yh = m ? d_tbh : d_tah; }
    else            { xh = m ? d_tbh : d_tah; y = m ? d_td : d_tc; yh = nullptr; }
    const uint2* __restrict__ x4 = (const uint2*)xh;
    const uint2* __restrict__ ce = d_ce[m];

    int s = d_rp[m][r], e = d_rp[m][r + 1];
    float4 acc = make_float4(0.f, 0.f, 0.f, 0.f);
    int j = s;
    for (; j + 1 < e; j += 2) {
        uint2 e0 = ce[j], e1 = ce[j + 1];
        float v0 = __uint_as_float(e0.y);
        float v1 = __uint_as_float(e1.y);
        uint2 p0 = x4[(size_t)e0.x * 64 + cq];
        uint2 p1 = x4[(size_t)e1.x * 64 + cq];
        float2 f0 = __half22float2(*(const __half2*)&p0.x);
        float2 f1 = __half22float2(*(const __half2*)&p0.y);
        float2 g0 = __half22float2(*(const __half2*)&p1.x);
        float2 g1 = __half22float2(*(const __half2*)&p1.y);
        acc.x = fmaf(v0, f0.x, acc.x); acc.y = fmaf(v0, f0.y, acc.y);
        acc.z = fmaf(v0, f1.x, acc.z); acc.w = fmaf(v0, f1.y, acc.w);
        acc.x = fmaf(v1, g0.x, acc.x); acc.y = fmaf(v1, g0.y, acc.y);
        acc.z = fmaf(v1, g1.x, acc.z); acc.w = fmaf(v1, g1.y, acc.w);
    }
    if (j < e) {
        uint2 e0 = ce[j];
        float v = __uint_as_float(e0.y);
        uint2 p0 = x4[(size_t)e0.x * 64 + cq];
        float2 f0 = __half22float2(*(const __half2*)&p0.x);
        float2 f1 = __half22float2(*(const __half2*)&p0.y);
        acc.x = fmaf(v, f0.x, acc.x); acc.y = fmaf(v, f0.y, acc.y);
        acc.z = fmaf(v, f1.x, acc.z); acc.w = fmaf(v, f1.y, acc.w);
    }
    ((float4*)y)[(size_t)r * 64 + cq] = acc;
    if (PHASE == 0) {
        __half2 h0 = __floats2half2_rn(acc.x, acc.y);
        __half2 h1 = __floats2half2_rn(acc.z, acc.w);
        uint2 o;
        o.x = *reinterpret_cast<uint32_t*>(&h0);
        o.y = *reinterpret_cast<uint32_t*>(&h1);
        ((uint2*)yh)[(size_t)r * 64 + cq] = o;
    }
}

// ---------------- combine: hadamard with alpha restart ----------------
__global__ void k_combine() {
    int i = blockIdx.x * blockDim.x + threadIdx.x;
    const float4* tc = (const float4*)d_tc;
    const float4* td = (const float4*)d_td;
    const float4* hs = (const float4*)d_hs;
    const float4* ht = (const float4*)d_ht;
    float4 a = tc[i], h = hs[i];
    float4 b = td[i], g = ht[i];
    float4 o;
    o.x = (a.x + 0.1f * h.x) * (b.x + 0.1f * g.x);
    o.y = (a.y + 0.1f * h.y) * (b.y + 0.1f * g.y);
    o.z = (a.z + 0.1f * h.z) * (b.z + 0.1f * g.z);
    o.w = (a.w + 0.1f * h.w) * (b.w + 0.1f * g.w);
    ((float4*)d_ta)[i] = o;
}

// ---------------- GEMM1: tf32 mma.sync, split-K ----------------
__device__ __forceinline__ float rnd_tf32(float v) {
    return __int_as_float(__float_as_int(v) + 0x1000);
}

__device__ __forceinline__ void mma_tf32(float& c0, float& c1, float& c2, float& c3,
                                         uint32_t a0, uint32_t a1, uint32_t a2, uint32_t a3,
                                         uint32_t b0, uint32_t b1) {
    asm volatile(
        "mma.sync.aligned.m16n8k8.row.col.f32.tf32.tf32.f32 "
        "{%0,%1,%2,%3},{%4,%5,%6,%7},{%8,%9},{%0,%1,%2,%3};"
        : "+f"(c0), "+f"(c1), "+f"(c2), "+f"(c3)
        : "r"(a0), "r"(a1), "r"(a2), "r"(a3), "r"(b0), "r"(b1));
}

__global__ void __launch_bounds__(256) k_gemm1(const float* __restrict__ W1) {
    __shared__ float As[BK][LDA];
    __shared__ float Bs[BK][LDB];
    const int m0 = blockIdx.x * BM;
    const int n0 = blockIdx.y * BN;
    const int kbase = blockIdx.z * KC;
    const int tid = threadIdx.x;
    const int lane = tid & 31;
    const int wid = tid >> 5;
    const int wm = (wid >> 2) * 64;
    const int wn = (wid & 3) * 32;
    const int gid = lane >> 2;
    const int tig = lane & 3;
    const int am = (tid & 31) * 4;
    const int ak = tid >> 5;
    const int bn = tid & 127;
    const int bkq = (tid >> 7) * 16;

    const float* __restrict__ A = d_ta;
    float4 ra[4], rb[4];
    float acc[4][4][4];
#pragma unroll
    for (int i = 0; i < 4; i++)
#pragma unroll
        for (int j = 0; j < 4; j++)
#pragma unroll
            for (int q = 0; q < 4; q++) acc[i][j][q] = 0.f;

#pragma unroll
    for (int p = 0; p < 4; p++)
        ra[p] = *(const float4*)&A[(size_t)(kbase + ak + p * 8) * BSZ + m0 + am];
#pragma unroll
    for (int p = 0; p < 4; p++)
        rb[p] = *(const float4*)&W1[(size_t)(n0 + bn) * G + kbase + bkq + p * 4];

    const int NSTAGE = KC / BK;
    for (int s = 0; s < NSTAGE; s++) {
        __syncthreads();
#pragma unroll
        for (int p = 0; p < 4; p++) {
            float4 v = ra[p];
            v.x = rnd_tf32(v.x); v.y = rnd_tf32(v.y);
            v.z = rnd_tf32(v.z); v.w = rnd_tf32(v.w);
            *(float4*)&As[ak + p * 8][am] = v;
        }
#pragma unroll
        for (int p = 0; p < 4; p++) {
            float4 v = rb[p];
            Bs[bkq + p * 4 + 0][bn] = rnd_tf32(v.x);
            Bs[bkq + p * 4 + 1][bn] = rnd_tf32(v.y);
            Bs[bkq + p * 4 + 2][bn] = rnd_tf32(v.z);
            Bs[bkq + p * 4 + 3][bn] = rnd_tf32(v.w);
        }
        __syncthreads();
        if (s + 1 < NSTAGE) {
            int kb = kbase + (s + 1) * BK;
#pragma unroll
            for (int p = 0; p < 4; p++)
                ra[p] = *(const float4*)&A[(size_t)(kb + ak + p * 8) * BSZ + m0 + am];
#pragma unroll
            for (int p = 0; p < 4; p++)
                rb[p] = *(const float4*)&W1[(size_t)(n0 + bn) * G + kb + bkq + p * 4];
        }
#pragma unroll
        for (int ks = 0; ks < 4; ks++) {
            int k0 = ks * 8;
            uint32_t af[4][4], bf[4][2];
#pragma unroll
            for (int i = 0; i < 4; i++) {
                int rm = wm + i * 16 + gid;
                af[i][0] = __float_as_uint(As[k0 + tig][rm]);
                af[i][1] = __float_as_uint(As[k0 + tig][rm + 8]);
                af[i][2] = __float_as_uint(As[k0 + tig + 4][rm]);
                af[i][3] = __float_as_uint(As[k0 + tig + 4][rm + 8]);
            }
#pragma unroll
            for (int j = 0; j < 4; j++) {
                int cn = wn + j * 8 + gid;
                bf[j][0] = __float_as_uint(Bs[k0 + tig][cn]);
                bf[j][1] = __float_as_uint(Bs[k0 + tig + 4][cn]);
            }
#pragma unroll
            for (int i = 0; i < 4; i++)
#pragma unroll
                for (int j = 0; j < 4; j++)
                    mma_tf32(acc[i][j][0], acc[i][j][1], acc[i][j][2], acc[i][j][3],
                             af[i][0], af[i][1], af[i][2], af[i][3],
                             bf[j][0], bf[j][1]);
        }
    }

    float* out = d_part + (size_t)blockIdx.z * BSZ * H1;
#pragma unroll
    for (int i = 0; i < 4; i++) {
        int row = m0 + wm + i * 16 + gid;
#pragma unroll
        for (int j = 0; j < 4; j++) {
            int col = n0 + wn + j * 8 + 2 * tig;
            float2 lo = make_float2(acc[i][j][0], acc[i][j][1]);
            float2 hi = make_float2(acc[i][j][2], acc[i][j][3]);
            *(float2*)&out[(size_t)row * H1 + col] = lo;
            *(float2*)&out[(size_t)(row + 8) * H1 + col] = hi;
        }
    }
}

__global__ void k_reduce1(const float* __restrict__ b1) {
    int i = blockIdx.x * blockDim.x + threadIdx.x;
    int n = i & (H1 - 1);
    float s = b1[n];
#pragma unroll
    for (int z = 0; z < ZSPLIT; z++)
        s += d_part[(size_t)z * BSZ * H1 + i];
    d_h1[i] = fmaxf(s, 0.f);
}

// ---------------- GEMM2 ----------------
__global__ void k_gemm2(const float* __restrict__ W2, const float* __restrict__ b2) {
    __shared__ float sh[4][H1];
    int b0 = blockIdx.x * 4;
    int n = threadIdx.x;
#pragma unroll
    for (int r = 0; r < 4; r++)
        for (int k = n; k < H1; k += H2)
            sh[r][k] = d_h1[(size_t)(b0 + r) * H1 + k];
    __syncthreads();
    float bias = b2[n];
    float a0 = bias, a1 = bias, a2 = bias, a3 = bias;
    const float4* w = (const float4*)(W2 + (size_t)n * H1);
#pragma unroll 4
    for (int kk = 0; kk < H1 / 4; kk++) {
        float4 wv = w[kk];
        a0 = fmaf(wv.x, sh[0][kk * 4 + 0], a0); a0 = fmaf(wv.y, sh[0][kk * 4 + 1], a0);
        a0 = fmaf(wv.z, sh[0][kk * 4 + 2], a0); a0 = fmaf(wv.w, sh[0][kk * 4 + 3], a0);
        a1 = fmaf(wv.x, sh[1][kk * 4 + 0], a1); a1 = fmaf(wv.y, sh[1][kk * 4 + 1], a1);
        a1 = fmaf(wv.z, sh[1][kk * 4 + 2], a1); a1 = fmaf(wv.w, sh[1][kk * 4 + 3], a1);
        a2 = fmaf(wv.x, sh[2][kk * 4 + 0], a2); a2 = fmaf(wv.y, sh[2][kk * 4 + 1], a2);
        a2 = fmaf(wv.z, sh[2][kk * 4 + 2], a2); a2 = fmaf(wv.w, sh[2][kk * 4 + 3], a2);
        a3 = fmaf(wv.x, sh[3][kk * 4 + 0], a3); a3 = fmaf(wv.y, sh[3][kk * 4 + 1], a3);
        a3 = fmaf(wv.z, sh[3][kk * 4 + 2], a3); a3 = fmaf(wv.w, sh[3][kk * 4 + 3], a3);
    }
    d_h2[(size_t)(b0 + 0) * H2 + n] = fmaxf(a0, 0.f);
    d_h2[(size_t)(b0 + 1) * H2 + n] = fmaxf(a1, 0.f);
    d_h2[(size_t)(b0 + 2) * H2 + n] = fmaxf(a2, 0.f);
    d_h2[(size_t)(b0 + 3) * H2 + n] = fmaxf(a3, 0.f);
}

// ---------------- GEMM3 ----------------
__global__ void k_gemm3(const float* __restrict__ W3, const float* __restrict__ b3,
                        float* __restrict__ out) {
    __shared__ float sh[H2];
    int b = blockIdx.x;
    int tid = threadIdx.x;
    sh[tid] = d_h2[(size_t)b * H2 + tid];
    __syncthreads();
    if (tid < NCLS) {
        float acc = b3[tid];
        const float* w = W3 + (size_t)tid * H2;
#pragma unroll 4
        for (int k = 0; k < H2; k++)
            acc = fmaf(w[k], sh[k], acc);
        out[(size_t)b * NCLS + tid] = acc;
    }
}

// ---------------- launch ----------------
extern "C" void kernel_launch(void* const* d_in, const int* in_sizes, int n_in,
                              void* d_out, int out_size) {
    const float* x_sample  = (const float*)d_in[0];
    const float* x_TF      = (const float*)d_in[1];
    const int*   adj_rows  = (const int*)  d_in[2];
    const int*   adj_cols  = (const int*)  d_in[3];
    const float* adj_vals  = (const float*)d_in[4];
    const int*   adjT_rows = (const int*)  d_in[5];
    const int*   adjT_cols = (const int*)  d_in[6];
    const float* adjT_vals = (const float*)d_in[7];
    const float* emb_mut   = (const float*)d_in[8];
    const float* bias_mut  = (const float*)d_in[9];
    const float* emb_exp   = (const float*)d_in[10];
    const float* bias_exp  = (const float*)d_in[11];
    const float* W1        = (const float*)d_in[12];
    const float* b1        = (const float*)d_in[13];
    const float* W2        = (const float*)d_in[14];
    const float* b2        = (const float*)d_in[15];
    const float* W3        = (const float*)d_in[16];
    const float* b3        = (const float*)d_in[17];
    float* out = (float*)d_out;

    k_embed<<<dim3(G / 32, BSZ / 32), dim3(32, 8)>>>(x_sample, x_TF,
                                                     emb_mut, bias_mut, emb_exp, bias_exp);
    k_zero_cnt<<<(2 * G + 255) / 256, 256>>>();
    k_hist<<<(2 * NNZ + 255) / 256, 256>>>(adj_rows, adjT_rows);
    k_scan_part<<<dim3(NBLK, 2), SCANB>>>();
    k_scan_mid<<<1, 128>>>();
    k_scan_add<<<dim3(NBLK, 2), SCANB>>>();
    k_scatter<<<(2 * NNZ + 255) / 256, 256>>>(adj_rows, adj_cols, adj_vals,
                                              adjT_rows, adjT_cols, adjT_vals);
    k_spmm_dual<0><<<2 * G / 4, 256>>>();
    k_spmm_dual<1><<<2 * G / 4, 256>>>();
    k_combine<<<(G * BSZ / 4) / 256, 256>>>();
    k_gemm1<<<dim3(BSZ / BM, H1 / BN, ZSPLIT), 256>>>(W1);
    k_reduce1<<<(BSZ * H1) / 256, 256>>>(b1);
    k_gemm2<<<BSZ / 4, H2>>>(W2, b2);
    k_gemm3<<<BSZ, H2>>>(W3, b3, out);
}

// round 4
// speedup vs baseline: 2.9034x; 1.2300x over previous
#include <cuda_runtime.h>
#include <cuda_fp16.h>
#include <cstddef>
#include <cstdint>

#define G    20000
#define BSZ  256
#define NNZ  640000
#define H1   1024
#define H2   128
#define NCLS 33

// GEMM1 tiling
#define BM 128
#define BN 128
#define BK 32
#define ZSPLIT 25
#define KC 800
#define LDH 40        // SMEM row pitch in halves (80B, 16B-aligned, conflict-free)

#define SCANB 512
#define NBLK  40

// ---------------- scratch ----------------
__device__ float d_hs[(size_t)G * BSZ];
__device__ float d_ht[(size_t)G * BSZ];
__device__ float d_tc[(size_t)G * BSZ];
__device__ float d_td[(size_t)G * BSZ];

__device__ __half d_hsh[(size_t)G * BSZ];
__device__ __half d_hth[(size_t)G * BSZ];
__device__ __half d_tah[(size_t)G * BSZ];
__device__ __half d_tbh[(size_t)G * BSZ];
__device__ __half d_A16[(size_t)BSZ * G];   // hadamard, [B][G] fp16

__device__ int   d_cnt[2][G];
__device__ int   d_rp [2][G + 1];
__device__ int   d_ofs[2][G];
__device__ uint2 d_ce [2][NNZ];
__device__ int   d_bsum[2][NBLK];
__device__ int   d_bmid[2][NBLK];

__device__ float d_part[(size_t)ZSPLIT * BSZ * H1];
__device__ float d_h1[(size_t)BSZ * H1];
__device__ float d_h2[(size_t)BSZ * H2];

// ---------------- embed ----------------
__global__ void k_embed(const float* __restrict__ xs_in, const float* __restrict__ xt_in,
                        const float* __restrict__ em, const float* __restrict__ bm,
                        const float* __restrict__ ee, const float* __restrict__ be) {
    __shared__ float s0[32][33];
    __shared__ float s1[32][33];
    const float EM = em[0], BM_ = bm[0], EE = ee[0], BE = be[0];
    int g0 = blockIdx.x * 32;
    int b0 = blockIdx.y * 32;
    int tx = threadIdx.x, ty = threadIdx.y;
#pragma unroll
    for (int r = 0; r < 4; r++) {
        size_t idx = (size_t)(b0 + ty + r * 8) * G + g0 + tx;
        s0[ty + r * 8][tx] = xs_in[idx];
        s1[ty + r * 8][tx] = xt_in[idx];
    }
    __syncthreads();
#pragma unroll
    for (int r = 0; r < 4; r++) {
        int g = g0 + ty + r * 8;
        int b = b0 + tx;
        size_t idx = (size_t)g * BSZ + b;
        float vs = fmaxf(fmaf(EM, s0[tx][ty + r * 8], BM_), 0.f);
        float vt = fmaxf(fmaf(EE, s1[tx][ty + r * 8], BE), 0.f);
        d_hs[idx] = vs;  d_hsh[idx] = __float2half_rn(vs);
        d_ht[idx] = vt;  d_hth[idx] = __float2half_rn(vt);
    }
}

// ---------------- CSR build ----------------
__global__ void k_zero_cnt() {
    int i = blockIdx.x * blockDim.x + threadIdx.x;
    if (i < 2 * G) ((int*)d_cnt)[i] = 0;
}

__global__ void k_hist(const int* __restrict__ r0, const int* __restrict__ r1) {
    int i = blockIdx.x * blockDim.x + threadIdx.x;
    if (i < NNZ) {
        atomicAdd(&d_cnt[0][r0[i]], 1);
    } else if (i < 2 * NNZ) {
        atomicAdd(&d_cnt[1][r1[i - NNZ]], 1);
    }
}

__global__ void k_scan_part() {
    int m = blockIdx.y;
    int tid = threadIdx.x;
    int i = blockIdx.x * SCANB + tid;
    int lane = tid & 31, w = tid >> 5;
    int c = (i < G) ? d_cnt[m][i] : 0;
    int v = c;
#pragma unroll
    for (int off = 1; off < 32; off <<= 1) {
        int u = __shfl_up_sync(0xffffffffu, v, off);
        if (lane >= off) v += u;
    }
    __shared__ int ws[16];
    if (lane == 31) ws[w] = v;
    __syncthreads();
    if (w == 0) {
        int x = (lane < 16) ? ws[lane] : 0;
#pragma unroll
        for (int off = 1; off < 16; off <<= 1) {
            int u = __shfl_up_sync(0xffffffffu, x, off);
            if (lane >= off) x += u;
        }
        if (lane < 16) ws[lane] = x;
    }
    __syncthreads();
    int excl = v - c + ((w > 0) ? ws[w - 1] : 0);
    if (i < G) d_rp[m][i] = excl;
    if (tid == SCANB - 1) d_bsum[m][blockIdx.x] = excl + c;
}

__global__ void k_scan_mid() {
    int tid = threadIdx.x;
    int m = tid >> 6;
    int t = tid & 63;
    int lane = tid & 31, warp = tid >> 5;
    int c = (t < NBLK) ? d_bsum[m][t] : 0;
    int v = c;
#pragma unroll
    for (int off = 1; off < 32; off <<= 1) {
        int u = __shfl_up_sync(0xffffffffu, v, off);
        if (lane >= off) v += u;
    }
    __shared__ int tot[4];
    if (lane == 31) tot[warp] = v;
    __syncthreads();
    int add = (warp & 1) ? tot[warp - 1] : 0;
    int excl = v - c + add;
    if (t < NBLK) d_bmid[m][t] = excl;
}

__global__ void k_scan_add() {
    int m = blockIdx.y;
    int i = blockIdx.x * SCANB + threadIdx.x;
    int add = d_bmid[m][blockIdx.x];
    if (i < G) {
        int r = d_rp[m][i] + add;
        d_rp[m][i] = r;
        d_ofs[m][i] = r;
    }
    if (blockIdx.x == 0 && threadIdx.x == 0) d_rp[m][G] = NNZ;
}

__global__ void k_scatter(const int* __restrict__ r0, const int* __restrict__ c0, const float* __restrict__ v0,
                          const int* __restrict__ r1, const int* __restrict__ c1, const float* __restrict__ v1) {
    int i = blockIdx.x * blockDim.x + threadIdx.x;
    if (i < NNZ) {
        int r = r0[i];
        int p = atomicAdd(&d_ofs[0][r], 1);
        d_ce[0][p] = make_uint2((unsigned)c0[i], __float_as_uint(0.9f * v0[i]));
    } else if (i < 2 * NNZ) {
        int j = i - NNZ;
        int r = r1[j];
        int p = atomicAdd(&d_ofs[1][r], 1);
        d_ce[1][p] = make_uint2((unsigned)c1[j], __float_as_uint(0.9f * v1[j]));
    }
}

// ---------------- SpMM: fp16 gather, fp32 accumulate ----------------
template <int PHASE>
__global__ void k_spmm_dual() {
    int tid = threadIdx.x;
    int gr = blockIdx.x * 4 + (tid >> 6);
    int cq = tid & 63;
    int m = (gr >= G) ? 1 : 0;
    int r = gr - m * G;

    const __half* __restrict__ xh;
    float* __restrict__ y = nullptr;
    __half* __restrict__ yh = nullptr;
    if (PHASE == 0) { xh = m ? d_hth : d_hsh; yh = m ? d_tbh : d_tah; }
    else            { xh = m ? d_tbh : d_tah; y = m ? d_td : d_tc; }
    const uint2* __restrict__ x4 = (const uint2*)xh;
    const uint2* __restrict__ ce = d_ce[m];

    int s = d_rp[m][r], e = d_rp[m][r + 1];
    float4 acc = make_float4(0.f, 0.f, 0.f, 0.f);
    int j = s;
    for (; j + 1 < e; j += 2) {
        uint2 e0 = ce[j], e1 = ce[j + 1];
        float v0 = __uint_as_float(e0.y);
        float v1 = __uint_as_float(e1.y);
        uint2 p0 = x4[(size_t)e0.x * 64 + cq];
        uint2 p1 = x4[(size_t)e1.x * 64 + cq];
        float2 f0 = __half22float2(*(const __half2*)&p0.x);
        float2 f1 = __half22float2(*(const __half2*)&p0.y);
        float2 g0 = __half22float2(*(const __half2*)&p1.x);
        float2 g1 = __half22float2(*(const __half2*)&p1.y);
        acc.x = fmaf(v0, f0.x, acc.x); acc.y = fmaf(v0, f0.y, acc.y);
        acc.z = fmaf(v0, f1.x, acc.z); acc.w = fmaf(v0, f1.y, acc.w);
        acc.x = fmaf(v1, g0.x, acc.x); acc.y = fmaf(v1, g0.y, acc.y);
        acc.z = fmaf(v1, g1.x, acc.z); acc.w = fmaf(v1, g1.y, acc.w);
    }
    if (j < e) {
        uint2 e0 = ce[j];
        float v = __uint_as_float(e0.y);
        uint2 p0 = x4[(size_t)e0.x * 64 + cq];
        float2 f0 = __half22float2(*(const __half2*)&p0.x);
        float2 f1 = __half22float2(*(const __half2*)&p0.y);
        acc.x = fmaf(v, f0.x, acc.x); acc.y = fmaf(v, f0.y, acc.y);
        acc.z = fmaf(v, f1.x, acc.z); acc.w = fmaf(v, f1.y, acc.w);
    }
    if (PHASE == 0) {
        __half2 h0 = __floats2half2_rn(acc.x, acc.y);
        __half2 h1 = __floats2half2_rn(acc.z, acc.w);
        uint2 o;
        o.x = *reinterpret_cast<uint32_t*>(&h0);
        o.y = *reinterpret_cast<uint32_t*>(&h1);
        ((uint2*)yh)[(size_t)r * 64 + cq] = o;
    } else {
        ((float4*)y)[(size_t)r * 64 + cq] = acc;
    }
}

// ---------------- combine: hadamard -> fp16 [B][G] (transposed) ----------------
__global__ void k_combine_t() {
    __shared__ __half t[32][34];
    int g0 = blockIdx.x * 32;
    int b0 = blockIdx.y * 32;
    int tx = threadIdx.x, ty = threadIdx.y;
#pragma unroll
    for (int r = 0; r < 4; r++) {
        int g = g0 + ty + r * 8;
        size_t idx = (size_t)g * BSZ + b0 + tx;
        float a = d_tc[idx] + 0.1f * d_hs[idx];
        float b = d_td[idx] + 0.1f * d_ht[idx];
        t[ty + r * 8][tx] = __float2half_rn(a * b);
    }
    __syncthreads();
#pragma unroll
    for (int r = 0; r < 4; r++) {
        int b = b0 + ty + r * 8;
        int g = g0 + tx;
        d_A16[(size_t)b * G + g] = t[tx][ty + r * 8];
    }
}

// ---------------- GEMM1: fp16 mma.sync m16n8k16, fp32 acc, split-K ----------------
__device__ __forceinline__ void mma_f16(float& c0, float& c1, float& c2, float& c3,
                                        uint32_t a0, uint32_t a1, uint32_t a2, uint32_t a3,
                                        uint32_t b0, uint32_t b1) {
    asm volatile(
        "mma.sync.aligned.m16n8k16.row.col.f32.f16.f16.f32 "
        "{%0,%1,%2,%3},{%4,%5,%6,%7},{%8,%9},{%0,%1,%2,%3};"
        : "+f"(c0), "+f"(c1), "+f"(c2), "+f"(c3)
        : "r"(a0), "r"(a1), "r"(a2), "r"(a3), "r"(b0), "r"(b1));
}

__global__ void __launch_bounds__(256) k_gemm1(const float* __restrict__ W1) {
    __shared__ __half As[BM * LDH];   // [m][k], pitch 40 halves
    __shared__ __half Bs[BN * LDH];   // [n][k]
    const int m0 = blockIdx.x * BM;
    const int n0 = blockIdx.y * BN;
    const int kbase = blockIdx.z * KC;
    const int tid = threadIdx.x;
    const int lane = tid & 31;
    const int wid = tid >> 5;
    const int wm = (wid >> 2) * 64;
    const int wn = (wid & 3) * 32;
    const int gid = lane >> 2;
    const int tig = lane & 3;

    // staging coords: each thread owns half a row (32B of halves / 64B of floats)
    const int srow = tid >> 1;          // 0..127
    const int shalf = tid & 1;          // 0/1 -> k offset 0/16

    const __half* __restrict__ A = d_A16;
    uint4 ra[2];
    float4 rb[4];
    float acc[4][4][4];
#pragma unroll
    for (int i = 0; i < 4; i++)
#pragma unroll
        for (int j = 0; j < 4; j++)
#pragma unroll
            for (int q = 0; q < 4; q++) acc[i][j][q] = 0.f;

    const size_t abase = (size_t)(m0 + srow) * G + kbase + shalf * 16;
    const size_t bbase = (size_t)(n0 + srow) * G + kbase + shalf * 16;

    // prefetch stage 0
    ra[0] = *(const uint4*)&A[abase];
    ra[1] = *(const uint4*)&A[abase + 8];
#pragma unroll
    for (int p = 0; p < 4; p++)
        rb[p] = *(const float4*)&W1[bbase + p * 4];

    uint4* AsStore = (uint4*)&As[srow * LDH + shalf * 16];
    uint4* BsStore = (uint4*)&Bs[srow * LDH + shalf * 16];
    const uint32_t* As32 = (const uint32_t*)As;
    const uint32_t* Bs32 = (const uint32_t*)Bs;

    const int NSTAGE = KC / BK;   // 25
    for (int s = 0; s < NSTAGE; s++) {
        __syncthreads();
        AsStore[0] = ra[0];
        AsStore[1] = ra[1];
        {
            __half2 h[8];
            h[0] = __floats2half2_rn(rb[0].x, rb[0].y);
            h[1] = __floats2half2_rn(rb[0].z, rb[0].w);
            h[2] = __floats2half2_rn(rb[1].x, rb[1].y);
            h[3] = __floats2half2_rn(rb[1].z, rb[1].w);
            h[4] = __floats2half2_rn(rb[2].x, rb[2].y);
            h[5] = __floats2half2_rn(rb[2].z, rb[2].w);
            h[6] = __floats2half2_rn(rb[3].x, rb[3].y);
            h[7] = __floats2half2_rn(rb[3].z, rb[3].w);
            BsStore[0] = *(uint4*)&h[0];
            BsStore[1] = *(uint4*)&h[4];
        }
        __syncthreads();
        if (s + 1 < NSTAGE) {
            size_t ao = abase + (size_t)(s + 1) * BK;
            size_t bo = bbase + (size_t)(s + 1) * BK;
            ra[0] = *(const uint4*)&A[ao];
            ra[1] = *(const uint4*)&A[ao + 8];
#pragma unroll
            for (int p = 0; p < 4; p++)
                rb[p] = *(const float4*)&W1[bo + p * 4];
        }
#pragma unroll
        for (int ks = 0; ks < 2; ks++) {
            const int ko = ks * 8;   // k offset in u32 units (16 halves)
            uint32_t af[4][4], bf[4][2];
#pragma unroll
            for (int i = 0; i < 4; i++) {
                int rm = wm + i * 16 + gid;
                af[i][0] = As32[rm * (LDH / 2) + ko + tig];
                af[i][1] = As32[(rm + 8) * (LDH / 2) + ko + tig];
                af[i][2] = As32[rm * (LDH / 2) + ko + tig + 4];
                af[i][3] = As32[(rm + 8) * (LDH / 2) + ko + tig + 4];
            }
#pragma unroll
            for (int j = 0; j < 4; j++) {
                int cn = wn + j * 8 + gid;
                bf[j][0] = Bs32[cn * (LDH / 2) + ko + tig];
                bf[j][1] = Bs32[cn * (LDH / 2) + ko + tig + 4];
            }
#pragma unroll
            for (int i = 0; i < 4; i++)
#pragma unroll
                for (int j = 0; j < 4; j++)
                    mma_f16(acc[i][j][0], acc[i][j][1], acc[i][j][2], acc[i][j][3],
                            af[i][0], af[i][1], af[i][2], af[i][3],
                            bf[j][0], bf[j][1]);
        }
    }

    float* out = d_part + (size_t)blockIdx.z * BSZ * H1;
#pragma unroll
    for (int i = 0; i < 4; i++) {
        int row = m0 + wm + i * 16 + gid;
#pragma unroll
        for (int j = 0; j < 4; j++) {
            int col = n0 + wn + j * 8 + 2 * tig;
            float2 lo = make_float2(acc[i][j][0], acc[i][j][1]);
            float2 hi = make_float2(acc[i][j][2], acc[i][j][3]);
            *(float2*)&out[(size_t)row * H1 + col] = lo;
            *(float2*)&out[(size_t)(row + 8) * H1 + col] = hi;
        }
    }
}

__global__ void k_reduce1(const float* __restrict__ b1) {
    int i = blockIdx.x * blockDim.x + threadIdx.x;
    int n = i & (H1 - 1);
    float s = b1[n];
#pragma unroll
    for (int z = 0; z < ZSPLIT; z++)
        s += d_part[(size_t)z * BSZ * H1 + i];
    d_h1[i] = fmaxf(s, 0.f);
}

// ---------------- GEMM2 ----------------
__global__ void k_gemm2(const float* __restrict__ W2, const float* __restrict__ b2) {
    __shared__ float sh[4][H1];
    int b0 = blockIdx.x * 4;
    int n = threadIdx.x;
#pragma unroll
    for (int r = 0; r < 4; r++)
        for (int k = n; k < H1; k += H2)
            sh[r][k] = d_h1[(size_t)(b0 + r) * H1 + k];
    __syncthreads();
    float bias = b2[n];
    float a0 = bias, a1 = bias, a2 = bias, a3 = bias;
    const float4* w = (const float4*)(W2 + (size_t)n * H1);
#pragma unroll 4
    for (int kk = 0; kk < H1 / 4; kk++) {
        float4 wv = w[kk];
        a0 = fmaf(wv.x, sh[0][kk * 4 + 0], a0); a0 = fmaf(wv.y, sh[0][kk * 4 + 1], a0);
        a0 = fmaf(wv.z, sh[0][kk * 4 + 2], a0); a0 = fmaf(wv.w, sh[0][kk * 4 + 3], a0);
        a1 = fmaf(wv.x, sh[1][kk * 4 + 0], a1); a1 = fmaf(wv.y, sh[1][kk * 4 + 1], a1);
        a1 = fmaf(wv.z, sh[1][kk * 4 + 2], a1); a1 = fmaf(wv.w, sh[1][kk * 4 + 3], a1);
        a2 = fmaf(wv.x, sh[2][kk * 4 + 0], a2); a2 = fmaf(wv.y, sh[2][kk * 4 + 1], a2);
        a2 = fmaf(wv.z, sh[2][kk * 4 + 2], a2); a2 = fmaf(wv.w, sh[2][kk * 4 + 3], a2);
        a3 = fmaf(wv.x, sh[3][kk * 4 + 0], a3); a3 = fmaf(wv.y, sh[3][kk * 4 + 1], a3);
        a3 = fmaf(wv.z, sh[3][kk * 4 + 2], a3); a3 = fmaf(wv.w, sh[3][kk * 4 + 3], a3);
    }
    d_h2[(size_t)(b0 + 0) * H2 + n] = fmaxf(a0, 0.f);
    d_h2[(size_t)(b0 + 1) * H2 + n] = fmaxf(a1, 0.f);
    d_h2[(size_t)(b0 + 2) * H2 + n] = fmaxf(a2, 0.f);
    d_h2[(size_t)(b0 + 3) * H2 + n] = fmaxf(a3, 0.f);
}

// ---------------- GEMM3 ----------------
__global__ void k_gemm3(const float* __restrict__ W3, const float* __restrict__ b3,
                        float* __restrict__ out) {
    __shared__ float sh[H2];
    int b = blockIdx.x;
    int tid = threadIdx.x;
    sh[tid] = d_h2[(size_t)b * H2 + tid];
    __syncthreads();
    if (tid < NCLS) {
        float acc = b3[tid];
        const float* w = W3 + (size_t)tid * H2;
#pragma unroll 4
        for (int k = 0; k < H2; k++)
            acc = fmaf(w[k], sh[k], acc);
        out[(size_t)b * NCLS + tid] = acc;
    }
}

// ---------------- launch ----------------
extern "C" void kernel_launch(void* const* d_in, const int* in_sizes, int n_in,
                              void* d_out, int out_size) {
    const float* x_sample  = (const float*)d_in[0];
    const float* x_TF      = (const float*)d_in[1];
    const int*   adj_rows  = (const int*)  d_in[2];
    const int*   adj_cols  = (const int*)  d_in[3];
    const float* adj_vals  = (const float*)d_in[4];
    const int*   adjT_rows = (const int*)  d_in[5];
    const int*   adjT_cols = (const int*)  d_in[6];
    const float* adjT_vals = (const float*)d_in[7];
    const float* emb_mut   = (const float*)d_in[8];
    const float* bias_mut  = (const float*)d_in[9];
    const float* emb_exp   = (const float*)d_in[10];
    const float* bias_exp  = (const float*)d_in[11];
    const float* W1        = (const float*)d_in[12];
    const float* b1        = (const float*)d_in[13];
    const float* W2        = (const float*)d_in[14];
    const float* b2        = (const float*)d_in[15];
    const float* W3        = (const float*)d_in[16];
    const float* b3        = (const float*)d_in[17];
    float* out = (float*)d_out;

    k_embed<<<dim3(G / 32, BSZ / 32), dim3(32, 8)>>>(x_sample, x_TF,
                                                     emb_mut, bias_mut, emb_exp, bias_exp);
    k_zero_cnt<<<(2 * G + 255) / 256, 256>>>();
    k_hist<<<(2 * NNZ + 255) / 256, 256>>>(adj_rows, adjT_rows);
    k_scan_part<<<dim3(NBLK, 2), SCANB>>>();
    k_scan_mid<<<1, 128>>>();
    k_scan_add<<<dim3(NBLK, 2), SCANB>>>();
    k_scatter<<<(2 * NNZ + 255) / 256, 256>>>(adj_rows, adj_cols, adj_vals,
                                              adjT_rows, adjT_cols, adjT_vals);
    k_spmm_dual<0><<<2 * G / 4, 256>>>();
    k_spmm_dual<1><<<2 * G / 4, 256>>>();
    k_combine_t<<<dim3(G / 32, BSZ / 32), dim3(32, 8)>>>();
    k_gemm1<<<dim3(BSZ / BM, H1 / BN, ZSPLIT), 256>>>(W1);
    k_reduce1<<<(BSZ * H1) / 256, 256>>>(b1);
    k_gemm2<<<BSZ / 4, H2>>>(W2, b2);
    k_gemm3<<<BSZ, H2>>>(W3, b3, out);
}

// round 5
// speedup vs baseline: 3.0719x; 1.0580x over previous
#include <cuda_runtime.h>
#include <cuda_fp16.h>
#include <cstddef>
#include <cstdint>

#define G    20000
#define BSZ  256
#define NNZ  640000
#define H1   1024
#define H2   128
#define NCLS 33

// GEMM1 tiling
#define BM 128
#define BN 128
#define BK 32
#define ZSPLIT 25
#define KC 800
#define LDH 40        // SMEM row pitch in halves (80B)

#define SCANB 512
#define NBLK  40

// ---------------- scratch ----------------
__device__ float d_hs[(size_t)G * BSZ];
__device__ float d_ht[(size_t)G * BSZ];
__device__ float d_tc[(size_t)G * BSZ];
__device__ float d_td[(size_t)G * BSZ];

__device__ __half d_hsh[(size_t)G * BSZ];
__device__ __half d_hth[(size_t)G * BSZ];
__device__ __half d_tah[(size_t)G * BSZ];
__device__ __half d_tbh[(size_t)G * BSZ];
__device__ __half d_A16[(size_t)BSZ * G];   // hadamard, [B][G] fp16

__device__ int   d_cnt[2][G];
__device__ int   d_rp [2][G + 1];
__device__ int   d_ofs[2][G];
__device__ uint2 d_ce [2][NNZ];
__device__ int   d_bsum[2][NBLK];

__device__ float d_part[(size_t)ZSPLIT * BSZ * H1];
__device__ float d_h1[(size_t)BSZ * H1];
__device__ float d_h2[(size_t)BSZ * H2];

// ---------------- embed (+ zero d_cnt for the CSR build) ----------------
__global__ void k_embed(const float* __restrict__ xs_in, const float* __restrict__ xt_in,
                        const float* __restrict__ em, const float* __restrict__ bm,
                        const float* __restrict__ ee, const float* __restrict__ be) {
    // fold counter zeroing in (stream order places this before k_hist)
    int bid = blockIdx.y * gridDim.x + blockIdx.x;
    int tidl = threadIdx.y * 32 + threadIdx.x;
    int zi = bid * 256 + tidl;
    if (zi < 2 * G) ((int*)d_cnt)[zi] = 0;

    __shared__ float s0[32][33];
    __shared__ float s1[32][33];
    const float EM = em[0], BM_ = bm[0], EE = ee[0], BE = be[0];
    int g0 = blockIdx.x * 32;
    int b0 = blockIdx.y * 32;
    int tx = threadIdx.x, ty = threadIdx.y;
#pragma unroll
    for (int r = 0; r < 4; r++) {
        size_t idx = (size_t)(b0 + ty + r * 8) * G + g0 + tx;
        s0[ty + r * 8][tx] = xs_in[idx];
        s1[ty + r * 8][tx] = xt_in[idx];
    }
    __syncthreads();
#pragma unroll
    for (int r = 0; r < 4; r++) {
        int g = g0 + ty + r * 8;
        int b = b0 + tx;
        size_t idx = (size_t)g * BSZ + b;
        float vs = fmaxf(fmaf(EM, s0[tx][ty + r * 8], BM_), 0.f);
        float vt = fmaxf(fmaf(EE, s1[tx][ty + r * 8], BE), 0.f);
        d_hs[idx] = vs;  d_hsh[idx] = __float2half_rn(vs);
        d_ht[idx] = vt;  d_hth[idx] = __float2half_rn(vt);
    }
}

// ---------------- CSR build ----------------
__global__ void k_hist(const int* __restrict__ r0, const int* __restrict__ r1) {
    int i = blockIdx.x * blockDim.x + threadIdx.x;
    if (i < NNZ) {
        atomicAdd(&d_cnt[0][r0[i]], 1);
    } else if (i < 2 * NNZ) {
        atomicAdd(&d_cnt[1][r1[i - NNZ]], 1);
    }
}

__global__ void k_scan_part() {
    int m = blockIdx.y;
    int tid = threadIdx.x;
    int i = blockIdx.x * SCANB + tid;
    int lane = tid & 31, w = tid >> 5;
    int c = (i < G) ? d_cnt[m][i] : 0;
    int v = c;
#pragma unroll
    for (int off = 1; off < 32; off <<= 1) {
        int u = __shfl_up_sync(0xffffffffu, v, off);
        if (lane >= off) v += u;
    }
    __shared__ int ws[16];
    if (lane == 31) ws[w] = v;
    __syncthreads();
    if (w == 0) {
        int x = (lane < 16) ? ws[lane] : 0;
#pragma unroll
        for (int off = 1; off < 16; off <<= 1) {
            int u = __shfl_up_sync(0xffffffffu, x, off);
            if (lane >= off) x += u;
        }
        if (lane < 16) ws[lane] = x;
    }
    __syncthreads();
    int excl = v - c + ((w > 0) ? ws[w - 1] : 0);
    if (i < G) d_rp[m][i] = excl;
    if (tid == SCANB - 1) d_bsum[m][blockIdx.x] = excl + c;
}

// per-block: reduce the <=40 preceding block sums, then apply
__global__ void k_scan_add() {
    int m = blockIdx.y;
    __shared__ int sadd;
    int tid = threadIdx.x;
    if (tid < 32) {
        int bx = blockIdx.x;
        int s = 0;
        if (tid < bx) s += d_bsum[m][tid];
        if (tid + 32 < bx) s += d_bsum[m][tid + 32];
#pragma unroll
        for (int off = 16; off; off >>= 1) s += __shfl_xor_sync(0xffffffffu, s, off);
        if (tid == 0) sadd = s;
    }
    __syncthreads();
    int i = blockIdx.x * SCANB + tid;
    if (i < G) {
        int r = d_rp[m][i] + sadd;
        d_rp[m][i] = r;
        d_ofs[m][i] = r;
    }
    if (blockIdx.x == 0 && tid == 0) d_rp[m][G] = NNZ;
}

__global__ void k_scatter(const int* __restrict__ r0, const int* __restrict__ c0, const float* __restrict__ v0,
                          const int* __restrict__ r1, const int* __restrict__ c1, const float* __restrict__ v1) {
    int i = blockIdx.x * blockDim.x + threadIdx.x;
    if (i < NNZ) {
        int r = r0[i];
        int p = atomicAdd(&d_ofs[0][r], 1);
        d_ce[0][p] = make_uint2((unsigned)c0[i], __float_as_uint(0.9f * v0[i]));
    } else if (i < 2 * NNZ) {
        int j = i - NNZ;
        int r = r1[j];
        int p = atomicAdd(&d_ofs[1][r], 1);
        d_ce[1][p] = make_uint2((unsigned)c1[j], __float_as_uint(0.9f * v1[j]));
    }
}

// ---------------- SpMM: fp16 gather, fp32 accumulate, MLP=4 ----------------
__device__ __forceinline__ void fma_h2(float4& acc, float v, uint2 p) {
    float2 f0 = __half22float2(*(const __half2*)&p.x);
    float2 f1 = __half22float2(*(const __half2*)&p.y);
    acc.x = fmaf(v, f0.x, acc.x); acc.y = fmaf(v, f0.y, acc.y);
    acc.z = fmaf(v, f1.x, acc.z); acc.w = fmaf(v, f1.y, acc.w);
}

template <int PHASE>
__global__ void k_spmm_dual() {
    int tid = threadIdx.x;
    int gr = blockIdx.x * 4 + (tid >> 6);
    int cq = tid & 63;
    int m = (gr >= G) ? 1 : 0;
    int r = gr - m * G;

    const __half* __restrict__ xh;
    float* __restrict__ y = nullptr;
    __half* __restrict__ yh = nullptr;
    if (PHASE == 0) { xh = m ? d_hth : d_hsh; yh = m ? d_tbh : d_tah; }
    else            { xh = m ? d_tbh : d_tah; y = m ? d_td : d_tc; }
    const uint2* __restrict__ x4 = (const uint2*)xh;
    const uint2* __restrict__ ce = d_ce[m];

    int s = d_rp[m][r], e = d_rp[m][r + 1];
    float4 acc = make_float4(0.f, 0.f, 0.f, 0.f);
    int j = s;
    for (; j + 3 < e; j += 4) {
        uint2 e0 = ce[j], e1 = ce[j + 1], e2 = ce[j + 2], e3 = ce[j + 3];
        uint2 p0 = x4[(size_t)e0.x * 64 + cq];
        uint2 p1 = x4[(size_t)e1.x * 64 + cq];
        uint2 p2 = x4[(size_t)e2.x * 64 + cq];
        uint2 p3 = x4[(size_t)e3.x * 64 + cq];
        fma_h2(acc, __uint_as_float(e0.y), p0);
        fma_h2(acc, __uint_as_float(e1.y), p1);
        fma_h2(acc, __uint_as_float(e2.y), p2);
        fma_h2(acc, __uint_as_float(e3.y), p3);
    }
    for (; j < e; j++) {
        uint2 e0 = ce[j];
        fma_h2(acc, __uint_as_float(e0.y), x4[(size_t)e0.x * 64 + cq]);
    }
    if (PHASE == 0) {
        __half2 h0 = __floats2half2_rn(acc.x, acc.y);
        __half2 h1 = __floats2half2_rn(acc.z, acc.w);
        uint2 o;
        o.x = *reinterpret_cast<uint32_t*>(&h0);
        o.y = *reinterpret_cast<uint32_t*>(&h1);
        ((uint2*)yh)[(size_t)r * 64 + cq] = o;
    } else {
        ((float4*)y)[(size_t)r * 64 + cq] = acc;
    }
}

// ---------------- combine: hadamard -> fp16 [B][G] (transposed) ----------------
__global__ void k_combine_t() {
    __shared__ __half t[32][34];
    int g0 = blockIdx.x * 32;
    int b0 = blockIdx.y * 32;
    int tx = threadIdx.x, ty = threadIdx.y;
#pragma unroll
    for (int r = 0; r < 4; r++) {
        int g = g0 + ty + r * 8;
        size_t idx = (size_t)g * BSZ + b0 + tx;
        float a = d_tc[idx] + 0.1f * d_hs[idx];
        float b = d_td[idx] + 0.1f * d_ht[idx];
        t[ty + r * 8][tx] = __float2half_rn(a * b);
    }
    __syncthreads();
#pragma unroll
    for (int r = 0; r < 4; r++) {
        int b = b0 + ty + r * 8;
        int g = g0 + tx;
        d_A16[(size_t)b * G + g] = t[tx][ty + r * 8];
    }
}

// ---------------- GEMM1: fp16 mma.sync + ldmatrix, split-K ----------------
__device__ __forceinline__ void mma_f16(float& c0, float& c1, float& c2, float& c3,
                                        uint32_t a0, uint32_t a1, uint32_t a2, uint32_t a3,
                                        uint32_t b0, uint32_t b1) {
    asm volatile(
        "mma.sync.aligned.m16n8k16.row.col.f32.f16.f16.f32 "
        "{%0,%1,%2,%3},{%4,%5,%6,%7},{%8,%9},{%0,%1,%2,%3};"
        : "+f"(c0), "+f"(c1), "+f"(c2), "+f"(c3)
        : "r"(a0), "r"(a1), "r"(a2), "r"(a3), "r"(b0), "r"(b1));
}

__device__ __forceinline__ void ldsm4(uint32_t& r0, uint32_t& r1, uint32_t& r2, uint32_t& r3,
                                      uint32_t addr) {
    asm volatile("ldmatrix.sync.aligned.m8n8.x4.shared.b16 {%0,%1,%2,%3},[%4];"
                 : "=r"(r0), "=r"(r1), "=r"(r2), "=r"(r3) : "r"(addr));
}

__global__ void __launch_bounds__(256) k_gemm1(const float* __restrict__ W1) {
    __shared__ __half As[BM * LDH];   // [m][k]
    __shared__ __half Bs[BN * LDH];   // [n][k]
    const int m0 = blockIdx.x * BM;
    const int n0 = blockIdx.y * BN;
    const int kbase = blockIdx.z * KC;
    const int tid = threadIdx.x;
    const int lane = tid & 31;
    const int wid = tid >> 5;
    const int wm = (wid >> 2) * 64;
    const int wn = (wid & 3) * 32;
    const int gid = lane >> 2;
    const int tig = lane & 3;

    const int srow = tid >> 1;
    const int shalf = tid & 1;

    const __half* __restrict__ A = d_A16;
    uint4 ra[2];
    float4 rb[4];
    float acc[4][4][4];
#pragma unroll
    for (int i = 0; i < 4; i++)
#pragma unroll
        for (int j = 0; j < 4; j++)
#pragma unroll
            for (int q = 0; q < 4; q++) acc[i][j][q] = 0.f;

    const size_t abase = (size_t)(m0 + srow) * G + kbase + shalf * 16;
    const size_t bbase = (size_t)(n0 + srow) * G + kbase + shalf * 16;

    ra[0] = *(const uint4*)&A[abase];
    ra[1] = *(const uint4*)&A[abase + 8];
#pragma unroll
    for (int p = 0; p < 4; p++)
        rb[p] = *(const float4*)&W1[bbase + p * 4];

    uint4* AsStore = (uint4*)&As[srow * LDH + shalf * 16];
    uint4* BsStore = (uint4*)&Bs[srow * LDH + shalf * 16];

    // ldmatrix per-lane base addresses
    // A 16x16 tile fragments: groups (k0 rows0-7, k0 rows8-15, k8 rows0-7, k8 rows8-15)
    const uint32_t as_smem = (uint32_t)__cvta_generic_to_shared(As);
    const uint32_t bs_smem = (uint32_t)__cvta_generic_to_shared(Bs);
    const uint32_t a_lm = as_smem + (uint32_t)(((wm + (lane & 15)) * LDH + (lane >> 4) * 8) * 2);
    // B pair tile (16 n-rows): groups (n0-7 k0, n0-7 k8, n8-15 k0, n8-15 k8)
    const uint32_t b_lm = bs_smem + (uint32_t)(((wn + (lane & 7) + (lane >> 4) * 8) * LDH
                                                + ((lane >> 3) & 1) * 8) * 2);

    const int NSTAGE = KC / BK;
    for (int s = 0; s < NSTAGE; s++) {
        __syncthreads();
        AsStore[0] = ra[0];
        AsStore[1] = ra[1];
        {
            __half2 h[8];
            h[0] = __floats2half2_rn(rb[0].x, rb[0].y);
            h[1] = __floats2half2_rn(rb[0].z, rb[0].w);
            h[2] = __floats2half2_rn(rb[1].x, rb[1].y);
            h[3] = __floats2half2_rn(rb[1].z, rb[1].w);
            h[4] = __floats2half2_rn(rb[2].x, rb[2].y);
            h[5] = __floats2half2_rn(rb[2].z, rb[2].w);
            h[6] = __floats2half2_rn(rb[3].x, rb[3].y);
            h[7] = __floats2half2_rn(rb[3].z, rb[3].w);
            BsStore[0] = *(uint4*)&h[0];
            BsStore[1] = *(uint4*)&h[4];
        }
        __syncthreads();
        if (s + 1 < NSTAGE) {
            size_t ao = abase + (size_t)(s + 1) * BK;
            size_t bo = bbase + (size_t)(s + 1) * BK;
            ra[0] = *(const uint4*)&A[ao];
            ra[1] = *(const uint4*)&A[ao + 8];
#pragma unroll
            for (int p = 0; p < 4; p++)
                rb[p] = *(const float4*)&W1[bo + p * 4];
        }
#pragma unroll
        for (int ks = 0; ks < 2; ks++) {
            uint32_t af[4][4], bf[4][2];
#pragma unroll
            for (int i = 0; i < 4; i++)
                ldsm4(af[i][0], af[i][1], af[i][2], af[i][3],
                      a_lm + (uint32_t)((i * 16 * LDH + ks * 16) * 2));
            ldsm4(bf[0][0], bf[0][1], bf[1][0], bf[1][1],
                  b_lm + (uint32_t)((ks * 16) * 2));
            ldsm4(bf[2][0], bf[2][1], bf[3][0], bf[3][1],
                  b_lm + (uint32_t)((16 * LDH + ks * 16) * 2));
#pragma unroll
            for (int i = 0; i < 4; i++)
#pragma unroll
                for (int j = 0; j < 4; j++)
                    mma_f16(acc[i][j][0], acc[i][j][1], acc[i][j][2], acc[i][j][3],
                            af[i][0], af[i][1], af[i][2], af[i][3],
                            bf[j][0], bf[j][1]);
        }
    }

    float* out = d_part + (size_t)blockIdx.z * BSZ * H1;
#pragma unroll
    for (int i = 0; i < 4; i++) {
        int row = m0 + wm + i * 16 + gid;
#pragma unroll
        for (int j = 0; j < 4; j++) {
            int col = n0 + wn + j * 8 + 2 * tig;
            float2 lo = make_float2(acc[i][j][0], acc[i][j][1]);
            float2 hi = make_float2(acc[i][j][2], acc[i][j][3]);
            *(float2*)&out[(size_t)row * H1 + col] = lo;
            *(float2*)&out[(size_t)(row + 8) * H1 + col] = hi;
        }
    }
}

__global__ void k_reduce1(const float* __restrict__ b1) {
    int i = blockIdx.x * blockDim.x + threadIdx.x;
    int n = i & (H1 - 1);
    float s = b1[n];
#pragma unroll
    for (int z = 0; z < ZSPLIT; z++)
        s += d_part[(size_t)z * BSZ * H1 + i];
    d_h1[i] = fmaxf(s, 0.f);
}

// ---------------- GEMM2 ----------------
__global__ void k_gemm2(const float* __restrict__ W2, const float* __restrict__ b2) {
    __shared__ float sh[4][H1];
    int b0 = blockIdx.x * 4;
    int n = threadIdx.x;
#pragma unroll
    for (int r = 0; r < 4; r++)
        for (int k = n; k < H1; k += H2)
            sh[r][k] = d_h1[(size_t)(b0 + r) * H1 + k];
    __syncthreads();
    float bias = b2[n];
    float a0 = bias, a1 = bias, a2 = bias, a3 = bias;
    const float4* w = (const float4*)(W2 + (size_t)n * H1);
#pragma unroll 4
    for (int kk = 0; kk < H1 / 4; kk++) {
        float4 wv = w[kk];
        a0 = fmaf(wv.x, sh[0][kk * 4 + 0], a0); a0 = fmaf(wv.y, sh[0][kk * 4 + 1], a0);
        a0 = fmaf(wv.z, sh[0][kk * 4 + 2], a0); a0 = fmaf(wv.w, sh[0][kk * 4 + 3], a0);
        a1 = fmaf(wv.x, sh[1][kk * 4 + 0], a1); a1 = fmaf(wv.y, sh[1][kk * 4 + 1], a1);
        a1 = fmaf(wv.z, sh[1][kk * 4 + 2], a1); a1 = fmaf(wv.w, sh[1][kk * 4 + 3], a1);
        a2 = fmaf(wv.x, sh[2][kk * 4 + 0], a2); a2 = fmaf(wv.y, sh[2][kk * 4 + 1], a2);
        a2 = fmaf(wv.z, sh[2][kk * 4 + 2], a2); a2 = fmaf(wv.w, sh[2][kk * 4 + 3], a2);
        a3 = fmaf(wv.x, sh[3][kk * 4 + 0], a3); a3 = fmaf(wv.y, sh[3][kk * 4 + 1], a3);
        a3 = fmaf(wv.z, sh[3][kk * 4 + 2], a3); a3 = fmaf(wv.w, sh[3][kk * 4 + 3], a3);
    }
    d_h2[(size_t)(b0 + 0) * H2 + n] = fmaxf(a0, 0.f);
    d_h2[(size_t)(b0 + 1) * H2 + n] = fmaxf(a1, 0.f);
    d_h2[(size_t)(b0 + 2) * H2 + n] = fmaxf(a2, 0.f);
    d_h2[(size_t)(b0 + 3) * H2 + n] = fmaxf(a3, 0.f);
}

// ---------------- GEMM3 ----------------
__global__ void k_gemm3(const float* __restrict__ W3, const float* __restrict__ b3,
                        float* __restrict__ out) {
    __shared__ float sh[H2];
    int b = blockIdx.x;
    int tid = threadIdx.x;
    sh[tid] = d_h2[(size_t)b * H2 + tid];
    __syncthreads();
    if (tid < NCLS) {
        float acc = b3[tid];
        const float* w = W3 + (size_t)tid * H2;
#pragma unroll 4
        for (int k = 0; k < H2; k++)
            acc = fmaf(w[k], sh[k], acc);
        out[(size_t)b * NCLS + tid] = acc;
    }
}

// ---------------- launch ----------------
extern "C" void kernel_launch(void* const* d_in, const int* in_sizes, int n_in,
                              void* d_out, int out_size) {
    const float* x_sample  = (const float*)d_in[0];
    const float* x_TF      = (const float*)d_in[1];
    const int*   adj_rows  = (const int*)  d_in[2];
    const int*   adj_cols  = (const int*)  d_in[3];
    const float* adj_vals  = (const float*)d_in[4];
    const int*   adjT_rows = (const int*)  d_in[5];
    const int*   adjT_cols = (const int*)  d_in[6];
    const float* adjT_vals = (const float*)d_in[7];
    const float* emb_mut   = (const float*)d_in[8];
    const float* bias_mut  = (const float*)d_in[9];
    const float* emb_exp   = (const float*)d_in[10];
    const float* bias_exp  = (const float*)d_in[11];
    const float* W1        = (const float*)d_in[12];
    const float* b1        = (const float*)d_in[13];
    const float* W2        = (const float*)d_in[14];
    const float* b2        = (const float*)d_in[15];
    const float* W3        = (const float*)d_in[16];
    const float* b3        = (const float*)d_in[17];
    float* out = (float*)d_out;

    k_embed<<<dim3(G / 32, BSZ / 32), dim3(32, 8)>>>(x_sample, x_TF,
                                                     emb_mut, bias_mut, emb_exp, bias_exp);
    k_hist<<<(2 * NNZ + 255) / 256, 256>>>(adj_rows, adjT_rows);
    k_scan_part<<<dim3(NBLK, 2), SCANB>>>();
    k_scan_add<<<dim3(NBLK, 2), SCANB>>>();
    k_scatter<<<(2 * NNZ + 255) / 256, 256>>>(adj_rows, adj_cols, adj_vals,
                                              adjT_rows, adjT_cols, adjT_vals);
    k_spmm_dual<0><<<2 * G / 4, 256>>>();
    k_spmm_dual<1><<<2 * G / 4, 256>>>();
    k_combine_t<<<dim3(G / 32, BSZ / 32), dim3(32, 8)>>>();
    k_gemm1<<<dim3(BSZ / BM, H1 / BN, ZSPLIT), 256>>>(W1);
    k_reduce1<<<(BSZ * H1) / 256, 256>>>(b1);
    k_gemm2<<<BSZ / 4, H2>>>(W2, b2);
    k_gemm3<<<BSZ, H2>>>(W3, b3, out);
}

// round 6
// speedup vs baseline: 3.2757x; 1.0663x over previous
#include <cuda_runtime.h>
#include <cuda_fp16.h>
#include <cstddef>
#include <cstdint>

#define G    20000
#define BSZ  256
#define NNZ  640000
#define H1   1024
#define H2   128
#define NCLS 33

// GEMM1 tiling
#define BM 128
#define BN 128
#define BK 32
#define ZSPLIT 25
#define KC 800
#define LDM 136       // As pitch in halves ([k][m] layout, conflict-free for ldsm.trans)
#define LDH 40        // Bs pitch in halves ([n][k] layout)

#define SCANB 512
#define NBLK  40

// ---------------- scratch ----------------
__device__ float d_hs[(size_t)G * BSZ];
__device__ float d_ht[(size_t)G * BSZ];

__device__ __half d_hsh[(size_t)G * BSZ];
__device__ __half d_hth[(size_t)G * BSZ];
__device__ __half d_tah[(size_t)G * BSZ];
__device__ __half d_tbh[(size_t)G * BSZ];
__device__ __half d_P16[(size_t)G * BSZ];   // hadamard, [G][B] fp16 (k-major A)

__device__ int   d_cnt[2][G];
__device__ int   d_rp [2][G + 1];
__device__ int   d_ofs[2][G];
__device__ uint2 d_ce [2][NNZ];

__device__ float d_part[(size_t)ZSPLIT * BSZ * H1];
__device__ float d_h1[(size_t)BSZ * H1];

// ---------------- embed (+ zero d_cnt) ----------------
__global__ void k_embed(const float* __restrict__ xs_in, const float* __restrict__ xt_in,
                        const float* __restrict__ em, const float* __restrict__ bm,
                        const float* __restrict__ ee, const float* __restrict__ be) {
    int bid = blockIdx.y * gridDim.x + blockIdx.x;
    int tidl = threadIdx.y * 32 + threadIdx.x;
    int zi = bid * 256 + tidl;
    if (zi < 2 * G) ((int*)d_cnt)[zi] = 0;

    __shared__ float s0[32][33];
    __shared__ float s1[32][33];
    const float EM = em[0], BM_ = bm[0], EE = ee[0], BE = be[0];
    int g0 = blockIdx.x * 32;
    int b0 = blockIdx.y * 32;
    int tx = threadIdx.x, ty = threadIdx.y;
#pragma unroll
    for (int r = 0; r < 4; r++) {
        size_t idx = (size_t)(b0 + ty + r * 8) * G + g0 + tx;
        s0[ty + r * 8][tx] = xs_in[idx];
        s1[ty + r * 8][tx] = xt_in[idx];
    }
    __syncthreads();
#pragma unroll
    for (int r = 0; r < 4; r++) {
        int g = g0 + ty + r * 8;
        int b = b0 + tx;
        size_t idx = (size_t)g * BSZ + b;
        float vs = fmaxf(fmaf(EM, s0[tx][ty + r * 8], BM_), 0.f);
        float vt = fmaxf(fmaf(EE, s1[tx][ty + r * 8], BE), 0.f);
        d_hs[idx] = vs;  d_hsh[idx] = __float2half_rn(vs);
        d_ht[idx] = vt;  d_hth[idx] = __float2half_rn(vt);
    }
}

// ---------------- CSR build ----------------
__global__ void k_hist(const int* __restrict__ r0, const int* __restrict__ r1) {
    int i = blockIdx.x * blockDim.x + threadIdx.x;
    if (i < NNZ) {
        atomicAdd(&d_cnt[0][r0[i]], 1);
    } else if (i < 2 * NNZ) {
        atomicAdd(&d_cnt[1][r1[i - NNZ]], 1);
    }
}

// one-pass scan: each block redundantly reduces all preceding counts
__global__ void k_scan_one() {
    int m = blockIdx.y;
    int bx = blockIdx.x;
    int tid = threadIdx.x;
    int lane = tid & 31, w = tid >> 5;
    __shared__ int ws[16];
    __shared__ int sprev;

    // 1) reduce counts [0, bx*SCANB) via int4 grid-stride
    int prev = 0;
    {
        int nprev = bx * SCANB;                  // multiple of 4
        const int4* c4 = (const int4*)d_cnt[m];
        for (int i = tid; i < nprev / 4; i += SCANB) {
            int4 v = c4[i];
            prev += v.x + v.y + v.z + v.w;
        }
#pragma unroll
        for (int off = 16; off; off >>= 1) prev += __shfl_xor_sync(0xffffffffu, prev, off);
        if (lane == 0) ws[w] = prev;
        __syncthreads();
        if (tid == 0) {
            int s = 0;
#pragma unroll
            for (int i = 0; i < 16; i++) s += ws[i];
            sprev = s;
        }
    }
    __syncthreads();

    // 2) local scan of this block's 512
    int i = bx * SCANB + tid;
    int c = (i < G) ? d_cnt[m][i] : 0;
    int v = c;
#pragma unroll
    for (int off = 1; off < 32; off <<= 1) {
        int u = __shfl_up_sync(0xffffffffu, v, off);
        if (lane >= off) v += u;
    }
    __syncthreads();   // ws reuse
    if (lane == 31) ws[w] = v;
    __syncthreads();
    if (w == 0) {
        int x = (lane < 16) ? ws[lane] : 0;
#pragma unroll
        for (int off = 1; off < 16; off <<= 1) {
            int u = __shfl_up_sync(0xffffffffu, x, off);
            if (lane >= off) x += u;
        }
        if (lane < 16) ws[lane] = x;
    }
    __syncthreads();
    int excl = sprev + v - c + ((w > 0) ? ws[w - 1] : 0);
    if (i < G) {
        d_rp[m][i]  = excl;
        d_ofs[m][i] = excl;
    }
    if (bx == 0 && tid == 0) d_rp[m][G] = NNZ;
}

__global__ void k_scatter(const int* __restrict__ r0, const int* __restrict__ c0, const float* __restrict__ v0,
                          const int* __restrict__ r1, const int* __restrict__ c1, const float* __restrict__ v1) {
    int i = blockIdx.x * blockDim.x + threadIdx.x;
    if (i < NNZ) {
        int r = r0[i];
        int p = atomicAdd(&d_ofs[0][r], 1);
        d_ce[0][p] = make_uint2((unsigned)c0[i], __float_as_uint(0.9f * v0[i]));
    } else if (i < 2 * NNZ) {
        int j = i - NNZ;
        int r = r1[j];
        int p = atomicAdd(&d_ofs[1][r], 1);
        d_ce[1][p] = make_uint2((unsigned)c1[j], __float_as_uint(0.9f * v1[j]));
    }
}

// ---------------- SpMM helpers ----------------
__device__ __forceinline__ void fma_h2(float4& acc, float v, uint2 p) {
    float2 f0 = __half22float2(*(const __half2*)&p.x);
    float2 f1 = __half22float2(*(const __half2*)&p.y);
    acc.x = fmaf(v, f0.x, acc.x); acc.y = fmaf(v, f0.y, acc.y);
    acc.z = fmaf(v, f1.x, acc.z); acc.w = fmaf(v, f1.y, acc.w);
}

__device__ __forceinline__ float4 spmm_row(const uint2* __restrict__ ce,
                                           const uint2* __restrict__ x4,
                                           int s, int e, int cq) {
    float4 acc = make_float4(0.f, 0.f, 0.f, 0.f);
    int j = s;
    for (; j + 3 < e; j += 4) {
        uint2 e0 = ce[j], e1 = ce[j + 1], e2 = ce[j + 2], e3 = ce[j + 3];
        uint2 p0 = x4[(size_t)e0.x * 64 + cq];
        uint2 p1 = x4[(size_t)e1.x * 64 + cq];
        uint2 p2 = x4[(size_t)e2.x * 64 + cq];
        uint2 p3 = x4[(size_t)e3.x * 64 + cq];
        fma_h2(acc, __uint_as_float(e0.y), p0);
        fma_h2(acc, __uint_as_float(e1.y), p1);
        fma_h2(acc, __uint_as_float(e2.y), p2);
        fma_h2(acc, __uint_as_float(e3.y), p3);
    }
    for (; j < e; j++) {
        uint2 e0 = ce[j];
        fma_h2(acc, __uint_as_float(e0.y), x4[(size_t)e0.x * 64 + cq]);
    }
    return acc;
}

// phase 0: both matrices (grid 2G/4), fp16 out only
__global__ void k_spmm0() {
    int tid = threadIdx.x;
    int gr = blockIdx.x * 4 + (tid >> 6);
    int cq = tid & 63;
    int m = (gr >= G) ? 1 : 0;
    int r = gr - m * G;
    const uint2* x4 = (const uint2*)(m ? d_hth : d_hsh);
    __half* yh = m ? d_tbh : d_tah;

    float4 acc = spmm_row(d_ce[m], x4, d_rp[m][r], d_rp[m][r + 1], cq);

    __half2 h0 = __floats2half2_rn(acc.x, acc.y);
    __half2 h1 = __floats2half2_rn(acc.z, acc.w);
    uint2 o;
    o.x = *reinterpret_cast<uint32_t*>(&h0);
    o.y = *reinterpret_cast<uint32_t*>(&h1);
    ((uint2*)yh)[(size_t)r * 64 + cq] = o;
}

// phase 1 + alpha-restart + hadamard: grid G/4, writes d_P16 [G][B] fp16
__global__ void k_spmm_final() {
    int tid = threadIdx.x;
    int r = blockIdx.x * 4 + (tid >> 6);
    int cq = tid & 63;

    float4 as = spmm_row(d_ce[0], (const uint2*)d_tah, d_rp[0][r], d_rp[0][r + 1], cq);
    float4 at = spmm_row(d_ce[1], (const uint2*)d_tbh, d_rp[1][r], d_rp[1][r + 1], cq);

    float4 hs4 = ((const float4*)d_hs)[(size_t)r * 64 + cq];
    float4 ht4 = ((const float4*)d_ht)[(size_t)r * 64 + cq];
    float px = (as.x + 0.1f * hs4.x) * (at.x + 0.1f * ht4.x);
    float py = (as.y + 0.1f * hs4.y) * (at.y + 0.1f * ht4.y);
    float pz = (as.z + 0.1f * hs4.z) * (at.z + 0.1f * ht4.z);
    float pw = (as.w + 0.1f * hs4.w) * (at.w + 0.1f * ht4.w);

    __half2 h0 = __floats2half2_rn(px, py);
    __half2 h1 = __floats2half2_rn(pz, pw);
    uint2 o;
    o.x = *reinterpret_cast<uint32_t*>(&h0);
    o.y = *reinterpret_cast<uint32_t*>(&h1);
    ((uint2*)d_P16)[(size_t)r * 64 + cq] = o;
}

// ---------------- GEMM1: fp16 mma.sync, A k-major via ldmatrix.trans ----------------
__device__ __forceinline__ void mma_f16(float& c0, float& c1, float& c2, float& c3,
                                        uint32_t a0, uint32_t a1, uint32_t a2, uint32_t a3,
                                        uint32_t b0, uint32_t b1) {
    asm volatile(
        "mma.sync.aligned.m16n8k16.row.col.f32.f16.f16.f32 "
        "{%0,%1,%2,%3},{%4,%5,%6,%7},{%8,%9},{%0,%1,%2,%3};"
        : "+f"(c0), "+f"(c1), "+f"(c2), "+f"(c3)
        : "r"(a0), "r"(a1), "r"(a2), "r"(a3), "r"(b0), "r"(b1));
}

__device__ __forceinline__ void ldsm4(uint32_t& r0, uint32_t& r1, uint32_t& r2, uint32_t& r3,
                                      uint32_t addr) {
    asm volatile("ldmatrix.sync.aligned.m8n8.x4.shared.b16 {%0,%1,%2,%3},[%4];"
                 : "=r"(r0), "=r"(r1), "=r"(r2), "=r"(r3) : "r"(addr));
}

__device__ __forceinline__ void ldsm4t(uint32_t& r0, uint32_t& r1, uint32_t& r2, uint32_t& r3,
                                       uint32_t addr) {
    asm volatile("ldmatrix.sync.aligned.m8n8.x4.trans.shared.b16 {%0,%1,%2,%3},[%4];"
                 : "=r"(r0), "=r"(r1), "=r"(r2), "=r"(r3) : "r"(addr));
}

__global__ void __launch_bounds__(256) k_gemm1(const float* __restrict__ W1) {
    __shared__ __half As[BK * LDM];   // [k][m], pitch 136
    __shared__ __half Bs[BN * LDH];   // [n][k], pitch 40
    const int m0 = blockIdx.x * BM;
    const int n0 = blockIdx.y * BN;
    const int kbase = blockIdx.z * KC;
    const int tid = threadIdx.x;
    const int lane = tid & 31;
    const int wid = tid >> 5;
    const int wm = (wid >> 2) * 64;
    const int wn = (wid & 3) * 32;
    const int gid = lane >> 2;
    const int tig = lane & 3;

    // A staging: thread loads 16 halves of row k at m-segment
    const int akrow = tid >> 3;           // 0..31
    const int amseg = (tid & 7) * 16;     // halves
    // B staging (fp32->fp16 convert)
    const int srow = tid >> 1;
    const int shalf = tid & 1;

    const __half* __restrict__ A = d_P16;
    uint4 ra[2];
    float4 rb[4];
    float acc[4][4][4];
#pragma unroll
    for (int i = 0; i < 4; i++)
#pragma unroll
        for (int j = 0; j < 4; j++)
#pragma unroll
            for (int q = 0; q < 4; q++) acc[i][j][q] = 0.f;

    const size_t abase = (size_t)(kbase + akrow) * BSZ + m0 + amseg;
    const size_t bbase = (size_t)(n0 + srow) * G + kbase + shalf * 16;

    ra[0] = *(const uint4*)&A[abase];
    ra[1] = *(const uint4*)&A[abase + 8];
#pragma unroll
    for (int p = 0; p < 4; p++)
        rb[p] = *(const float4*)&W1[bbase + p * 4];

    uint4* AsStore = (uint4*)&As[akrow * LDM + amseg];
    uint4* BsStore = (uint4*)&Bs[srow * LDH + shalf * 16];

    const uint32_t as_smem = (uint32_t)__cvta_generic_to_shared(As);
    const uint32_t bs_smem = (uint32_t)__cvta_generic_to_shared(Bs);
    // A ldmatrix.trans lane address: row k = (lane&7) + ((lane>>4)&1)*8, col m = wm + ((lane>>3)&1)*8
    const uint32_t a_lm = as_smem +
        (uint32_t)((((lane & 7) + ((lane >> 4) & 1) * 8) * LDM + wm + ((lane >> 3) & 1) * 8) * 2);
    // B ldmatrix (normal) lane address (as before)
    const uint32_t b_lm = bs_smem + (uint32_t)(((wn + (lane & 7) + (lane >> 4) * 8) * LDH
                                                + ((lane >> 3) & 1) * 8) * 2);

    const int NSTAGE = KC / BK;
    for (int s = 0; s < NSTAGE; s++) {
        __syncthreads();
        AsStore[0] = ra[0];
        AsStore[1] = ra[1];
        {
            __half2 h[8];
            h[0] = __floats2half2_rn(rb[0].x, rb[0].y);
            h[1] = __floats2half2_rn(rb[0].z, rb[0].w);
            h[2] = __floats2half2_rn(rb[1].x, rb[1].y);
            h[3] = __floats2half2_rn(rb[1].z, rb[1].w);
            h[4] = __floats2half2_rn(rb[2].x, rb[2].y);
            h[5] = __floats2half2_rn(rb[2].z, rb[2].w);
            h[6] = __floats2half2_rn(rb[3].x, rb[3].y);
            h[7] = __floats2half2_rn(rb[3].z, rb[3].w);
            BsStore[0] = *(uint4*)&h[0];
            BsStore[1] = *(uint4*)&h[4];
        }
        __syncthreads();
        if (s + 1 < NSTAGE) {
            size_t ao = abase + (size_t)(s + 1) * BK * BSZ;
            size_t bo = bbase + (size_t)(s + 1) * BK;
            ra[0] = *(const uint4*)&A[ao];
            ra[1] = *(const uint4*)&A[ao + 8];
#pragma unroll
            for (int p = 0; p < 4; p++)
                rb[p] = *(const float4*)&W1[bo + p * 4];
        }
#pragma unroll
        for (int ks = 0; ks < 2; ks++) {
            uint32_t af[4][4], bf[4][2];
#pragma unroll
            for (int i = 0; i < 4; i++)
                ldsm4t(af[i][0], af[i][1], af[i][2], af[i][3],
                       a_lm + (uint32_t)((ks * 16 * LDM + i * 16) * 2));
            ldsm4(bf[0][0], bf[0][1], bf[1][0], bf[1][1],
                  b_lm + (uint32_t)((ks * 16) * 2));
            ldsm4(bf[2][0], bf[2][1], bf[3][0], bf[3][1],
                  b_lm + (uint32_t)((16 * LDH + ks * 16) * 2));
#pragma unroll
            for (int i = 0; i < 4; i++)
#pragma unroll
                for (int j = 0; j < 4; j++)
                    mma_f16(acc[i][j][0], acc[i][j][1], acc[i][j][2], acc[i][j][3],
                            af[i][0], af[i][1], af[i][2], af[i][3],
                            bf[j][0], bf[j][1]);
        }
    }

    float* out = d_part + (size_t)blockIdx.z * BSZ * H1;
#pragma unroll
    for (int i = 0; i < 4; i++) {
        int row = m0 + wm + i * 16 + gid;
#pragma unroll
        for (int j = 0; j < 4; j++) {
            int col = n0 + wn + j * 8 + 2 * tig;
            float2 lo = make_float2(acc[i][j][0], acc[i][j][1]);
            float2 hi = make_float2(acc[i][j][2], acc[i][j][3]);
            *(float2*)&out[(size_t)row * H1 + col] = lo;
            *(float2*)&out[(size_t)(row + 8) * H1 + col] = hi;
        }
    }
}

__global__ void k_reduce1(const float* __restrict__ b1) {
    int i = blockIdx.x * blockDim.x + threadIdx.x;
    int n = i & (H1 - 1);
    float s = b1[n];
#pragma unroll
    for (int z = 0; z < ZSPLIT; z++)
        s += d_part[(size_t)z * BSZ * H1 + i];
    d_h1[i] = fmaxf(s, 0.f);
}

// ---------------- GEMM2 + GEMM3 fused ----------------
__global__ void k_gemm23(const float* __restrict__ W2, const float* __restrict__ b2,
                         const float* __restrict__ W3, const float* __restrict__ b3,
                         float* __restrict__ out) {
    __shared__ float sh[4][H1];
    __shared__ float h2sm[4][132];
    int b0 = blockIdx.x * 4;
    int n = threadIdx.x;   // 128
#pragma unroll
    for (int r = 0; r < 4; r++)
        for (int k = n; k < H1; k += H2)
            sh[r][k] = d_h1[(size_t)(b0 + r) * H1 + k];
    __syncthreads();
    float bias = b2[n];
    float a0 = bias, a1 = bias, a2 = bias, a3 = bias;
    const float4* w = (const float4*)(W2 + (size_t)n * H1);
#pragma unroll 4
    for (int kk = 0; kk < H1 / 4; kk++) {
        float4 wv = w[kk];
        a0 = fmaf(wv.x, sh[0][kk * 4 + 0], a0); a0 = fmaf(wv.y, sh[0][kk * 4 + 1], a0);
        a0 = fmaf(wv.z, sh[0][kk * 4 + 2], a0); a0 = fmaf(wv.w, sh[0][kk * 4 + 3], a0);
        a1 = fmaf(wv.x, sh[1][kk * 4 + 0], a1); a1 = fmaf(wv.y, sh[1][kk * 4 + 1], a1);
        a1 = fmaf(wv.z, sh[1][kk * 4 + 2], a1); a1 = fmaf(wv.w, sh[1][kk * 4 + 3], a1);
        a2 = fmaf(wv.x, sh[2][kk * 4 + 0], a2); a2 = fmaf(wv.y, sh[2][kk * 4 + 1], a2);
        a2 = fmaf(wv.z, sh[2][kk * 4 + 2], a2); a2 = fmaf(wv.w, sh[2][kk * 4 + 3], a2);
        a3 = fmaf(wv.x, sh[3][kk * 4 + 0], a3); a3 = fmaf(wv.y, sh[3][kk * 4 + 1], a3);
        a3 = fmaf(wv.z, sh[3][kk * 4 + 2], a3); a3 = fmaf(wv.w, sh[3][kk * 4 + 3], a3);
    }
    h2sm[0][n] = fmaxf(a0, 0.f);
    h2sm[1][n] = fmaxf(a1, 0.f);
    h2sm[2][n] = fmaxf(a2, 0.f);
    h2sm[3][n] = fmaxf(a3, 0.f);
    __syncthreads();

    // gemm3: thread (rb = n&3, cls = n>>2); cls 32 by threads 0..3
    int rb = n & 3;
    int cls = n >> 2;
#pragma unroll 1
    for (int pass = 0; pass < 2; pass++) {
        int c = cls + pass * 32;
        if (pass == 1) { c = 32; rb = n; }
        if (pass == 1 && n >= 4) break;
        float acc = b3[c];
        const float4* w3 = (const float4*)(W3 + (size_t)c * H2);
        const float4* hv = (const float4*)h2sm[rb];
#pragma unroll 8
        for (int k = 0; k < H2 / 4; k++) {
            float4 wv = w3[k];
            float4 h = hv[k];
            acc = fmaf(wv.x, h.x, acc); acc = fmaf(wv.y, h.y, acc);
            acc = fmaf(wv.z, h.z, acc); acc = fmaf(wv.w, h.w, acc);
        }
        out[(size_t)(b0 + rb) * NCLS + c] = acc;
    }
}

// ---------------- launch ----------------
extern "C" void kernel_launch(void* const* d_in, const int* in_sizes, int n_in,
                              void* d_out, int out_size) {
    const float* x_sample  = (const float*)d_in[0];
    const float* x_TF      = (const float*)d_in[1];
    const int*   adj_rows  = (const int*)  d_in[2];
    const int*   adj_cols  = (const int*)  d_in[3];
    const float* adj_vals  = (const float*)d_in[4];
    const int*   adjT_rows = (const int*)  d_in[5];
    const int*   adjT_cols = (const int*)  d_in[6];
    const float* adjT_vals = (const float*)d_in[7];
    const float* emb_mut   = (const float*)d_in[8];
    const float* bias_mut  = (const float*)d_in[9];
    const float* emb_exp   = (const float*)d_in[10];
    const float* bias_exp  = (const float*)d_in[11];
    const float* W1        = (const float*)d_in[12];
    const float* b1        = (const float*)d_in[13];
    const float* W2        = (const float*)d_in[14];
    const float* b2        = (const float*)d_in[15];
    const float* W3        = (const float*)d_in[16];
    const float* b3        = (const float*)d_in[17];
    float* out = (float*)d_out;

    k_embed<<<dim3(G / 32, BSZ / 32), dim3(32, 8)>>>(x_sample, x_TF,
                                                     emb_mut, bias_mut, emb_exp, bias_exp);
    k_hist<<<(2 * NNZ + 255) / 256, 256>>>(adj_rows, adjT_rows);
    k_scan_one<<<dim3(NBLK, 2), SCANB>>>();
    k_scatter<<<(2 * NNZ + 255) / 256, 256>>>(adj_rows, adj_cols, adj_vals,
                                              adjT_rows, adjT_cols, adjT_vals);
    k_spmm0<<<2 * G / 4, 256>>>();
    k_spmm_final<<<G / 4, 256>>>();
    k_gemm1<<<dim3(BSZ / BM, H1 / BN, ZSPLIT), 256>>>(W1);
    k_reduce1<<<(BSZ * H1) / 256, 256>>>(b1);
    k_gemm23<<<BSZ / 4, H2>>>(W2, b2, W3, b3, out);
}

// round 7
// speedup vs baseline: 3.3831x; 1.0328x over previous
#include <cuda_runtime.h>
#include <cuda_fp16.h>
#include <cstddef>
#include <cstdint>

#define G    20000
#define BSZ  256
#define NNZ  640000
#define H1   1024
#define H2   128
#define NCLS 33

// GEMM1 tiling
#define BM 128
#define BN 128
#define BK 32
#define ZSPLIT 25
#define KC 800
#define LDM 136       // As pitch in halves ([k][m], conflict-free for ldsm.trans)
#define LDH 40        // Bs pitch in halves ([n][k])

#define SCANB 512
#define NBLK  40

// ---------------- scratch ----------------
__device__ __half d_hsh[(size_t)G * BSZ];
__device__ __half d_hth[(size_t)G * BSZ];
__device__ __half d_tah[(size_t)G * BSZ];
__device__ __half d_tbh[(size_t)G * BSZ];
__device__ __half d_P16[(size_t)G * BSZ];   // hadamard, [G][B] fp16 (k-major A)

__device__ int   d_cnt[2][G];
__device__ int   d_rp [2][G + 1];
__device__ int   d_ofs[2][G];
__device__ uint2 d_ce [2][NNZ];

__device__ float d_part[(size_t)ZSPLIT * BSZ * H1];
__device__ float d_h1[(size_t)BSZ * H1];

// ---------------- embed (+ zero d_cnt) ----------------
__global__ void k_embed(const float* __restrict__ xs_in, const float* __restrict__ xt_in,
                        const float* __restrict__ em, const float* __restrict__ bm,
                        const float* __restrict__ ee, const float* __restrict__ be) {
    int bid = blockIdx.y * gridDim.x + blockIdx.x;
    int tidl = threadIdx.y * 32 + threadIdx.x;
    int zi = bid * 256 + tidl;
    if (zi < 2 * G) ((int*)d_cnt)[zi] = 0;

    __shared__ float s0[32][33];
    __shared__ float s1[32][33];
    const float EM = em[0], BM_ = bm[0], EE = ee[0], BE = be[0];
    int g0 = blockIdx.x * 32;
    int b0 = blockIdx.y * 32;
    int tx = threadIdx.x, ty = threadIdx.y;
#pragma unroll
    for (int r = 0; r < 4; r++) {
        size_t idx = (size_t)(b0 + ty + r * 8) * G + g0 + tx;
        s0[ty + r * 8][tx] = xs_in[idx];
        s1[ty + r * 8][tx] = xt_in[idx];
    }
    __syncthreads();
#pragma unroll
    for (int r = 0; r < 4; r++) {
        int g = g0 + ty + r * 8;
        int b = b0 + tx;
        size_t idx = (size_t)g * BSZ + b;
        float vs = fmaxf(fmaf(EM, s0[tx][ty + r * 8], BM_), 0.f);
        float vt = fmaxf(fmaf(EE, s1[tx][ty + r * 8], BE), 0.f);
        d_hsh[idx] = __float2half_rn(vs);
        d_hth[idx] = __float2half_rn(vt);
    }
}

// ---------------- CSR build (MLP=4 atomics) ----------------
__global__ void k_hist(const int* __restrict__ r0, const int* __restrict__ r1) {
    int i = blockIdx.x * blockDim.x + threadIdx.x;   // over 2*NNZ/4
    const int Q = NNZ / 4;
    if (i < Q) {
        int4 r = ((const int4*)r0)[i];
        atomicAdd(&d_cnt[0][r.x], 1);
        atomicAdd(&d_cnt[0][r.y], 1);
        atomicAdd(&d_cnt[0][r.z], 1);
        atomicAdd(&d_cnt[0][r.w], 1);
    } else if (i < 2 * Q) {
        int4 r = ((const int4*)r1)[i - Q];
        atomicAdd(&d_cnt[1][r.x], 1);
        atomicAdd(&d_cnt[1][r.y], 1);
        atomicAdd(&d_cnt[1][r.z], 1);
        atomicAdd(&d_cnt[1][r.w], 1);
    }
}

// one-pass scan
__global__ void k_scan_one() {
    int m = blockIdx.y;
    int bx = blockIdx.x;
    int tid = threadIdx.x;
    int lane = tid & 31, w = tid >> 5;
    __shared__ int ws[16];
    __shared__ int sprev;

    int prev = 0;
    {
        int nprev = bx * SCANB;
        const int4* c4 = (const int4*)d_cnt[m];
        for (int i = tid; i < nprev / 4; i += SCANB) {
            int4 v = c4[i];
            prev += v.x + v.y + v.z + v.w;
        }
#pragma unroll
        for (int off = 16; off; off >>= 1) prev += __shfl_xor_sync(0xffffffffu, prev, off);
        if (lane == 0) ws[w] = prev;
        __syncthreads();
        if (tid == 0) {
            int s = 0;
#pragma unroll
            for (int i = 0; i < 16; i++) s += ws[i];
            sprev = s;
        }
    }
    __syncthreads();

    int i = bx * SCANB + tid;
    int c = (i < G) ? d_cnt[m][i] : 0;
    int v = c;
#pragma unroll
    for (int off = 1; off < 32; off <<= 1) {
        int u = __shfl_up_sync(0xffffffffu, v, off);
        if (lane >= off) v += u;
    }
    __syncthreads();
    if (lane == 31) ws[w] = v;
    __syncthreads();
    if (w == 0) {
        int x = (lane < 16) ? ws[lane] : 0;
#pragma unroll
        for (int off = 1; off < 16; off <<= 1) {
            int u = __shfl_up_sync(0xffffffffu, x, off);
            if (lane >= off) x += u;
        }
        if (lane < 16) ws[lane] = x;
    }
    __syncthreads();
    int excl = sprev + v - c + ((w > 0) ? ws[w - 1] : 0);
    if (i < G) {
        d_rp[m][i]  = excl;
        d_ofs[m][i] = excl;
    }
    if (bx == 0 && tid == 0) d_rp[m][G] = NNZ;
}

__global__ void k_scatter(const int* __restrict__ r0, const int* __restrict__ c0, const float* __restrict__ v0,
                          const int* __restrict__ r1, const int* __restrict__ c1, const float* __restrict__ v1) {
    int i = blockIdx.x * blockDim.x + threadIdx.x;   // over 2*NNZ/4
    const int Q = NNZ / 4;
    int m;
    int4 r, c;
    float4 v;
    if (i < Q) {
        m = 0;
        r = ((const int4*)r0)[i];
        c = ((const int4*)c0)[i];
        v = ((const float4*)v0)[i];
    } else if (i < 2 * Q) {
        m = 1;
        r = ((const int4*)r1)[i - Q];
        c = ((const int4*)c1)[i - Q];
        v = ((const float4*)v1)[i - Q];
    } else return;
    int* ofs = d_ofs[m];
    int p0 = atomicAdd(&ofs[r.x], 1);
    int p1 = atomicAdd(&ofs[r.y], 1);
    int p2 = atomicAdd(&ofs[r.z], 1);
    int p3 = atomicAdd(&ofs[r.w], 1);
    uint2* ce = d_ce[m];
    ce[p0] = make_uint2((unsigned)c.x, __float_as_uint(0.9f * v.x));
    ce[p1] = make_uint2((unsigned)c.y, __float_as_uint(0.9f * v.y));
    ce[p2] = make_uint2((unsigned)c.z, __float_as_uint(0.9f * v.z));
    ce[p3] = make_uint2((unsigned)c.w, __float_as_uint(0.9f * v.w));
}

// ---------------- SpMM helpers ----------------
__device__ __forceinline__ void fma_h2(float4& acc, float v, uint2 p) {
    float2 f0 = __half22float2(*(const __half2*)&p.x);
    float2 f1 = __half22float2(*(const __half2*)&p.y);
    acc.x = fmaf(v, f0.x, acc.x); acc.y = fmaf(v, f0.y, acc.y);
    acc.z = fmaf(v, f1.x, acc.z); acc.w = fmaf(v, f1.y, acc.w);
}

__device__ __forceinline__ float4 spmm_row(const uint2* __restrict__ ce,
                                           const uint2* __restrict__ x4,
                                           int s, int e, int cq) {
    float4 acc = make_float4(0.f, 0.f, 0.f, 0.f);
    int j = s;
    for (; j + 3 < e; j += 4) {
        uint2 e0 = ce[j], e1 = ce[j + 1], e2 = ce[j + 2], e3 = ce[j + 3];
        uint2 p0 = x4[(size_t)e0.x * 64 + cq];
        uint2 p1 = x4[(size_t)e1.x * 64 + cq];
        uint2 p2 = x4[(size_t)e2.x * 64 + cq];
        uint2 p3 = x4[(size_t)e3.x * 64 + cq];
        fma_h2(acc, __uint_as_float(e0.y), p0);
        fma_h2(acc, __uint_as_float(e1.y), p1);
        fma_h2(acc, __uint_as_float(e2.y), p2);
        fma_h2(acc, __uint_as_float(e3.y), p3);
    }
    for (; j < e; j++) {
        uint2 e0 = ce[j];
        fma_h2(acc, __uint_as_float(e0.y), x4[(size_t)e0.x * 64 + cq]);
    }
    return acc;
}

// phase 0: both matrices
__global__ void k_spmm0() {
    int tid = threadIdx.x;
    int gr = blockIdx.x * 4 + (tid >> 6);
    int cq = tid & 63;
    int m = (gr >= G) ? 1 : 0;
    int r = gr - m * G;
    const uint2* x4 = (const uint2*)(m ? d_hth : d_hsh);
    __half* yh = m ? d_tbh : d_tah;

    float4 acc = spmm_row(d_ce[m], x4, d_rp[m][r], d_rp[m][r + 1], cq);

    __half2 h0 = __floats2half2_rn(acc.x, acc.y);
    __half2 h1 = __floats2half2_rn(acc.z, acc.w);
    uint2 o;
    o.x = *reinterpret_cast<uint32_t*>(&h0);
    o.y = *reinterpret_cast<uint32_t*>(&h1);
    ((uint2*)yh)[(size_t)r * 64 + cq] = o;
}

// phase 1 + alpha-restart + hadamard -> d_P16 [G][B] fp16
__global__ void k_spmm_final() {
    int tid = threadIdx.x;
    int r = blockIdx.x * 4 + (tid >> 6);
    int cq = tid & 63;

    float4 as = spmm_row(d_ce[0], (const uint2*)d_tah, d_rp[0][r], d_rp[0][r + 1], cq);
    float4 at = spmm_row(d_ce[1], (const uint2*)d_tbh, d_rp[1][r], d_rp[1][r + 1], cq);

    uint2 hp = ((const uint2*)d_hsh)[(size_t)r * 64 + cq];
    uint2 tp = ((const uint2*)d_hth)[(size_t)r * 64 + cq];
    float2 h0 = __half22float2(*(const __half2*)&hp.x);
    float2 h1 = __half22float2(*(const __half2*)&hp.y);
    float2 t0 = __half22float2(*(const __half2*)&tp.x);
    float2 t1 = __half22float2(*(const __half2*)&tp.y);

    float px = (as.x + 0.1f * h0.x) * (at.x + 0.1f * t0.x);
    float py = (as.y + 0.1f * h0.y) * (at.y + 0.1f * t0.y);
    float pz = (as.z + 0.1f * h1.x) * (at.z + 0.1f * t1.x);
    float pw = (as.w + 0.1f * h1.y) * (at.w + 0.1f * t1.y);

    __half2 o0 = __floats2half2_rn(px, py);
    __half2 o1 = __floats2half2_rn(pz, pw);
    uint2 o;
    o.x = *reinterpret_cast<uint32_t*>(&o0);
    o.y = *reinterpret_cast<uint32_t*>(&o1);
    ((uint2*)d_P16)[(size_t)r * 64 + cq] = o;
}

// ---------------- GEMM1: fp16 mma.sync, double-buffered SMEM ----------------
__device__ __forceinline__ void mma_f16(float& c0, float& c1, float& c2, float& c3,
                                        uint32_t a0, uint32_t a1, uint32_t a2, uint32_t a3,
                                        uint32_t b0, uint32_t b1) {
    asm volatile(
        "mma.sync.aligned.m16n8k16.row.col.f32.f16.f16.f32 "
        "{%0,%1,%2,%3},{%4,%5,%6,%7},{%8,%9},{%0,%1,%2,%3};"
        : "+f"(c0), "+f"(c1), "+f"(c2), "+f"(c3)
        : "r"(a0), "r"(a1), "r"(a2), "r"(a3), "r"(b0), "r"(b1));
}

__device__ __forceinline__ void ldsm4(uint32_t& r0, uint32_t& r1, uint32_t& r2, uint32_t& r3,
                                      uint32_t addr) {
    asm volatile("ldmatrix.sync.aligned.m8n8.x4.shared.b16 {%0,%1,%2,%3},[%4];"
                 : "=r"(r0), "=r"(r1), "=r"(r2), "=r"(r3) : "r"(addr));
}

__device__ __forceinline__ void ldsm4t(uint32_t& r0, uint32_t& r1, uint32_t& r2, uint32_t& r3,
                                       uint32_t addr) {
    asm volatile("ldmatrix.sync.aligned.m8n8.x4.trans.shared.b16 {%0,%1,%2,%3},[%4];"
                 : "=r"(r0), "=r"(r1), "=r"(r2), "=r"(r3) : "r"(addr));
}

#define ASZ (BK * LDM)
#define BSZH (BN * LDH)

__global__ void __launch_bounds__(256) k_gemm1(const float* __restrict__ W1) {
    __shared__ __half As[2][ASZ];
    __shared__ __half Bs[2][BSZH];
    const int m0 = blockIdx.x * BM;
    const int n0 = blockIdx.y * BN;
    const int kbase = blockIdx.z * KC;
    const int tid = threadIdx.x;
    const int lane = tid & 31;
    const int wid = tid >> 5;
    const int wm = (wid >> 2) * 64;
    const int wn = (wid & 3) * 32;
    const int gid = lane >> 2;
    const int tig = lane & 3;

    const int akrow = tid >> 3;
    const int amseg = (tid & 7) * 16;
    const int srow = tid >> 1;
    const int shalf = tid & 1;

    const __half* __restrict__ A = d_P16;
    uint4 ra[2];
    float4 rb[4];
    float acc[4][4][4];
#pragma unroll
    for (int i = 0; i < 4; i++)
#pragma unroll
        for (int j = 0; j < 4; j++)
#pragma unroll
            for (int q = 0; q < 4; q++) acc[i][j][q] = 0.f;

    const size_t abase = (size_t)(kbase + akrow) * BSZ + m0 + amseg;
    const size_t bbase = (size_t)(n0 + srow) * G + kbase + shalf * 16;

    const int aoff = akrow * LDM + amseg;
    const int boff = srow * LDH + shalf * 16;

    const uint32_t as_smem = (uint32_t)__cvta_generic_to_shared(&As[0][0]);
    const uint32_t bs_smem = (uint32_t)__cvta_generic_to_shared(&Bs[0][0]);
    const uint32_t a_lm0 = as_smem +
        (uint32_t)((((lane & 7) + ((lane >> 4) & 1) * 8) * LDM + wm + ((lane >> 3) & 1) * 8) * 2);
    const uint32_t b_lm0 = bs_smem + (uint32_t)(((wn + (lane & 7) + (lane >> 4) * 8) * LDH
                                                 + ((lane >> 3) & 1) * 8) * 2);

    // prologue: stage 0 into buf 0
    ra[0] = *(const uint4*)&A[abase];
    ra[1] = *(const uint4*)&A[abase + 8];
#pragma unroll
    for (int p = 0; p < 4; p++)
        rb[p] = *(const float4*)&W1[bbase + p * 4];
    *(uint4*)&As[0][aoff]     = ra[0];
    *(uint4*)&As[0][aoff + 8] = ra[1];
    {
        __half2 h[8];
        h[0] = __floats2half2_rn(rb[0].x, rb[0].y);
        h[1] = __floats2half2_rn(rb[0].z, rb[0].w);
        h[2] = __floats2half2_rn(rb[1].x, rb[1].y);
        h[3] = __floats2half2_rn(rb[1].z, rb[1].w);
        h[4] = __floats2half2_rn(rb[2].x, rb[2].y);
        h[5] = __floats2half2_rn(rb[2].z, rb[2].w);
        h[6] = __floats2half2_rn(rb[3].x, rb[3].y);
        h[7] = __floats2half2_rn(rb[3].z, rb[3].w);
        *(uint4*)&Bs[0][boff]     = *(uint4*)&h[0];
        *(uint4*)&Bs[0][boff + 8] = *(uint4*)&h[4];
    }
    __syncthreads();

    const int NSTAGE = KC / BK;   // 25
    for (int s = 0; s < NSTAGE; s++) {
        const int cur = s & 1;
        if (s + 1 < NSTAGE) {
            size_t ao = abase + (size_t)(s + 1) * BK * BSZ;
            size_t bo = bbase + (size_t)(s + 1) * BK;
            ra[0] = *(const uint4*)&A[ao];
            ra[1] = *(const uint4*)&A[ao + 8];
#pragma unroll
            for (int p = 0; p < 4; p++)
                rb[p] = *(const float4*)&W1[bo + p * 4];
        }
        const uint32_t a_lm = a_lm0 + cur * (ASZ * 2);
        const uint32_t b_lm = b_lm0 + cur * (BSZH * 2);
#pragma unroll
        for (int ks = 0; ks < 2; ks++) {
            uint32_t af[4][4], bf[4][2];
#pragma unroll
            for (int i = 0; i < 4; i++)
                ldsm4t(af[i][0], af[i][1], af[i][2], af[i][3],
                       a_lm + (uint32_t)((ks * 16 * LDM + i * 16) * 2));
            ldsm4(bf[0][0], bf[0][1], bf[1][0], bf[1][1],
                  b_lm + (uint32_t)((ks * 16) * 2));
            ldsm4(bf[2][0], bf[2][1], bf[3][0], bf[3][1],
                  b_lm + (uint32_t)((16 * LDH + ks * 16) * 2));
#pragma unroll
            for (int i = 0; i < 4; i++)
#pragma unroll
                for (int j = 0; j < 4; j++)
                    mma_f16(acc[i][j][0], acc[i][j][1], acc[i][j][2], acc[i][j][3],
                            af[i][0], af[i][1], af[i][2], af[i][3],
                            bf[j][0], bf[j][1]);
        }
        if (s + 1 < NSTAGE) {
            const int nxt = cur ^ 1;
            *(uint4*)&As[nxt][aoff]     = ra[0];
            *(uint4*)&As[nxt][aoff + 8] = ra[1];
            __half2 h[8];
            h[0] = __floats2half2_rn(rb[0].x, rb[0].y);
            h[1] = __floats2half2_rn(rb[0].z, rb[0].w);
            h[2] = __floats2half2_rn(rb[1].x, rb[1].y);
            h[3] = __floats2half2_rn(rb[1].z, rb[1].w);
            h[4] = __floats2half2_rn(rb[2].x, rb[2].y);
            h[5] = __floats2half2_rn(rb[2].z, rb[2].w);
            h[6] = __floats2half2_rn(rb[3].x, rb[3].y);
            h[7] = __floats2half2_rn(rb[3].z, rb[3].w);
            *(uint4*)&Bs[nxt][boff]     = *(uint4*)&h[0];
            *(uint4*)&Bs[nxt][boff + 8] = *(uint4*)&h[4];
            __syncthreads();
        }
    }

    float* out = d_part + (size_t)blockIdx.z * BSZ * H1;
#pragma unroll
    for (int i = 0; i < 4; i++) {
        int row = m0 + wm + i * 16 + gid;
#pragma unroll
        for (int j = 0; j < 4; j++) {
            int col = n0 + wn + j * 8 + 2 * tig;
            float2 lo = make_float2(acc[i][j][0], acc[i][j][1]);
            float2 hi = make_float2(acc[i][j][2], acc[i][j][3]);
            *(float2*)&out[(size_t)row * H1 + col] = lo;
            *(float2*)&out[(size_t)(row + 8) * H1 + col] = hi;
        }
    }
}

__global__ void k_reduce1(const float* __restrict__ b1) {
    int i = blockIdx.x * blockDim.x + threadIdx.x;
    int n = i & (H1 - 1);
    float s = b1[n];
#pragma unroll
    for (int z = 0; z < ZSPLIT; z++)
        s += d_part[(size_t)z * BSZ * H1 + i];
    d_h1[i] = fmaxf(s, 0.f);
}

// ---------------- GEMM2 + GEMM3 fused ----------------
__global__ void k_gemm23(const float* __restrict__ W2, const float* __restrict__ b2,
                         const float* __restrict__ W3, const float* __restrict__ b3,
                         float* __restrict__ out) {
    __shared__ float sh[4][H1];
    __shared__ float h2sm[4][132];
    int b0 = blockIdx.x * 4;
    int n = threadIdx.x;
#pragma unroll
    for (int r = 0; r < 4; r++)
        for (int k = n; k < H1; k += H2)
            sh[r][k] = d_h1[(size_t)(b0 + r) * H1 + k];
    __syncthreads();
    float bias = b2[n];
    float a0 = bias, a1 = bias, a2 = bias, a3 = bias;
    const float4* w = (const float4*)(W2 + (size_t)n * H1);
#pragma unroll 4
    for (int kk = 0; kk < H1 / 4; kk++) {
        float4 wv = w[kk];
        a0 = fmaf(wv.x, sh[0][kk * 4 + 0], a0); a0 = fmaf(wv.y, sh[0][kk * 4 + 1], a0);
        a0 = fmaf(wv.z, sh[0][kk * 4 + 2], a0); a0 = fmaf(wv.w, sh[0][kk * 4 + 3], a0);
        a1 = fmaf(wv.x, sh[1][kk * 4 + 0], a1); a1 = fmaf(wv.y, sh[1][kk * 4 + 1], a1);
        a1 = fmaf(wv.z, sh[1][kk * 4 + 2], a1); a1 = fmaf(wv.w, sh[1][kk * 4 + 3], a1);
        a2 = fmaf(wv.x, sh[2][kk * 4 + 0], a2); a2 = fmaf(wv.y, sh[2][kk * 4 + 1], a2);
        a2 = fmaf(wv.z, sh[2][kk * 4 + 2], a2); a2 = fmaf(wv.w, sh[2][kk * 4 + 3], a2);
        a3 = fmaf(wv.x, sh[3][kk * 4 + 0], a3); a3 = fmaf(wv.y, sh[3][kk * 4 + 1], a3);
        a3 = fmaf(wv.z, sh[3][kk * 4 + 2], a3); a3 = fmaf(wv.w, sh[3][kk * 4 + 3], a3);
    }
    h2sm[0][n] = fmaxf(a0, 0.f);
    h2sm[1][n] = fmaxf(a1, 0.f);
    h2sm[2][n] = fmaxf(a2, 0.f);
    h2sm[3][n] = fmaxf(a3, 0.f);
    __syncthreads();

    int rb = n & 3;
    int cls = n >> 2;
#pragma unroll 1
    for (int pass = 0; pass < 2; pass++) {
        int c = cls + pass * 32;
        if (pass == 1) { c = 32; rb = n; }
        if (pass == 1 && n >= 4) break;
        float acc = b3[c];
        const float4* w3 = (const float4*)(W3 + (size_t)c * H2);
        const float4* hv = (const float4*)h2sm[rb];
#pragma unroll 8
        for (int k = 0; k < H2 / 4; k++) {
            float4 wv = w3[k];
            float4 h = hv[k];
            acc = fmaf(wv.x, h.x, acc); acc = fmaf(wv.y, h.y, acc);
            acc = fmaf(wv.z, h.z, acc); acc = fmaf(wv.w, h.w, acc);
        }
        out[(size_t)(b0 + rb) * NCLS + c] = acc;
    }
}

// ---------------- launch ----------------
extern "C" void kernel_launch(void* const* d_in, const int* in_sizes, int n_in,
                              void* d_out, int out_size) {
    const float* x_sample  = (const float*)d_in[0];
    const float* x_TF      = (const float*)d_in[1];
    const int*   adj_rows  = (const int*)  d_in[2];
    const int*   adj_cols  = (const int*)  d_in[3];
    const float* adj_vals  = (const float*)d_in[4];
    const int*   adjT_rows = (const int*)  d_in[5];
    const int*   adjT_cols = (const int*)  d_in[6];
    const float* adjT_vals = (const float*)d_in[7];
    const float* emb_mut   = (const float*)d_in[8];
    const float* bias_mut  = (const float*)d_in[9];
    const float* emb_exp   = (const float*)d_in[10];
    const float* bias_exp  = (const float*)d_in[11];
    const float* W1        = (const float*)d_in[12];
    const float* b1        = (const float*)d_in[13];
    const float* W2        = (const float*)d_in[14];
    const float* b2        = (const float*)d_in[15];
    const float* W3        = (const float*)d_in[16];
    const float* b3        = (const float*)d_in[17];
    float* out = (float*)d_out;

    k_embed<<<dim3(G / 32, BSZ / 32), dim3(32, 8)>>>(x_sample, x_TF,
                                                     emb_mut, bias_mut, emb_exp, bias_exp);
    k_hist<<<(2 * (NNZ / 4) + 255) / 256, 256>>>(adj_rows, adjT_rows);
    k_scan_one<<<dim3(NBLK, 2), SCANB>>>();
    k_scatter<<<(2 * (NNZ / 4) + 255) / 256, 256>>>(adj_rows, adj_cols, adj_vals,
                                                    adjT_rows, adjT_cols, adjT_vals);
    k_spmm0<<<2 * G / 4, 256>>>();
    k_spmm_final<<<G / 4, 256>>>();
    k_gemm1<<<dim3(BSZ / BM, H1 / BN, ZSPLIT), 256>>>(W1);
    k_reduce1<<<(BSZ * H1) / 256, 256>>>(b1);
    k_gemm23<<<BSZ / 4, H2>>>(W2, b2, W3, b3, out);
}